// round 9
// baseline (speedup 1.0000x reference)
#include <cuda_runtime.h>
#include <cstdint>

#define L   1024
#define D   512
#define H   8
#define HD  64
#define EPSF 1e-5f
#define SZ  (H*L*HD)          // 524288 elems per [H][L][HD] tensor

// ---------------- scratch (device globals; no allocation) ----------------
__device__ float g_q [SZ];
__device__ float g_k [SZ];
__device__ float g_v [SZ];
__device__ float g_kc[SZ];
__device__ float g_vc[SZ];
__device__ float g_gate[H*L];
__device__ float g_gcum[H*L];
__device__ float g_unit[L*D];
__device__ float g_cpart[2*4*SZ];   // conv partials: [z][chunk][H][L][HD]
__device__ float g_T[H*16*4096];    // per-tile state blocks T_j[m][n]

// Balanced triangular task map: 40 tasks per head, each <=4 s-tiles.
__device__ __forceinline__ void task_map(int t, int& lb, int& ch)
{
    int g, base;
    if      (t < 4)  { g = 0; base = 0;  }
    else if (t < 12) { g = 1; base = 4;  }
    else if (t < 24) { g = 2; base = 12; }
    else             { g = 3; base = 24; }
    const int idx = t - base;
    lb = g * 4 + idx / (g + 1);
    ch = idx % (g + 1);
}

// ================= tf32 split-precision MMA machinery ====================
__device__ __forceinline__ uint32_t f2tf32(float x)
{
    uint32_t r; asm("cvt.rna.tf32.f32 %0, %1;" : "=r"(r) : "f"(x)); return r;
}

__device__ __forceinline__ void mma_tf32(float c[4],
                                         const uint32_t a[4],
                                         const uint32_t b[2])
{
    asm("mma.sync.aligned.m16n8k8.row.col.f32.tf32.tf32.f32 "
        "{%0,%1,%2,%3}, {%4,%5,%6,%7}, {%8,%9}, {%0,%1,%2,%3};"
        : "+f"(c[0]), "+f"(c[1]), "+f"(c[2]), "+f"(c[3])
        : "r"(a[0]), "r"(a[1]), "r"(a[2]), "r"(a[3]),
          "r"(b[0]), "r"(b[1]));
}

// C[m][n] = sum_k A[m][k] * B[n][k]; block tile 128x64, K=512, 256 threads.
// Warps: 4(m) x 2(n); warp tile 32x32 (2 m16-steps x 4 n8-steps).
// smem stride 20 makes fragment gathers bank-conflict-free.
#define TFS 20
__device__ __forceinline__ void tf32_gemm_128x64(
    const float* __restrict__ A, const float* __restrict__ B,
    int m0, int n0, float c[2][4][4],
    float* Ah, float* Al, float* Bh, float* Bl)
{
    const int tid  = threadIdx.x;
    const int lane = tid & 31;
    const int wid  = tid >> 5;
    const int mw   = wid >> 1;          // 0..3
    const int nw   = wid & 1;           // 0..1
    const int row  = lane >> 2;         // 0..7
    const int kq   = lane & 3;          // 0..3

    const uint32_t* uAh = (const uint32_t*)Ah;
    const uint32_t* uAl = (const uint32_t*)Al;
    const uint32_t* uBh = (const uint32_t*)Bh;
    const uint32_t* uBl = (const uint32_t*)Bl;

    for (int k0 = 0; k0 < 512; k0 += 16) {
        __syncthreads();
        // load A chunk: 128 rows x 16 cols
        #pragma unroll
        for (int it = 0; it < 2; it++) {
            const int idx = tid + it * 256;
            const int r   = idx >> 2;
            const int c4  = (idx & 3) << 2;
            float4 g = *(const float4*)(A + (m0 + r) * 512 + k0 + c4);
            float4 hi4, lo4;
            uint32_t h;
            h = f2tf32(g.x); hi4.x = __uint_as_float(h); lo4.x = __uint_as_float(f2tf32(g.x - hi4.x));
            h = f2tf32(g.y); hi4.y = __uint_as_float(h); lo4.y = __uint_as_float(f2tf32(g.y - hi4.y));
            h = f2tf32(g.z); hi4.z = __uint_as_float(h); lo4.z = __uint_as_float(f2tf32(g.z - hi4.z));
            h = f2tf32(g.w); hi4.w = __uint_as_float(h); lo4.w = __uint_as_float(f2tf32(g.w - hi4.w));
            *(float4*)(Ah + r * TFS + c4) = hi4;
            *(float4*)(Al + r * TFS + c4) = lo4;
        }
        // load B chunk: 64 rows x 16 cols
        {
            const int r  = tid >> 2;
            const int c4 = (tid & 3) << 2;
            float4 g = *(const float4*)(B + (n0 + r) * 512 + k0 + c4);
            float4 hi4, lo4;
            uint32_t h;
            h = f2tf32(g.x); hi4.x = __uint_as_float(h); lo4.x = __uint_as_float(f2tf32(g.x - hi4.x));
            h = f2tf32(g.y); hi4.y = __uint_as_float(h); lo4.y = __uint_as_float(f2tf32(g.y - hi4.y));
            h = f2tf32(g.z); hi4.z = __uint_as_float(h); lo4.z = __uint_as_float(f2tf32(g.z - hi4.z));
            h = f2tf32(g.w); hi4.w = __uint_as_float(h); lo4.w = __uint_as_float(f2tf32(g.w - hi4.w));
            *(float4*)(Bh + r * TFS + c4) = hi4;
            *(float4*)(Bl + r * TFS + c4) = lo4;
        }
        __syncthreads();

        #pragma unroll
        for (int k8 = 0; k8 < 16; k8 += 8) {
            uint32_t ah[2][4], al[2][4], bh[4][2], bl[4][2];
            #pragma unroll
            for (int ms = 0; ms < 2; ms++) {
                const int bi = (mw * 32 + ms * 16 + row) * TFS + k8 + kq;
                ah[ms][0] = uAh[bi];           ah[ms][1] = uAh[bi + 8*TFS];
                ah[ms][2] = uAh[bi + 4];       ah[ms][3] = uAh[bi + 8*TFS + 4];
                al[ms][0] = uAl[bi];           al[ms][1] = uAl[bi + 8*TFS];
                al[ms][2] = uAl[bi + 4];       al[ms][3] = uAl[bi + 8*TFS + 4];
            }
            #pragma unroll
            for (int ns = 0; ns < 4; ns++) {
                const int bi = (nw * 32 + ns * 8 + row) * TFS + k8 + kq;
                bh[ns][0] = uBh[bi];  bh[ns][1] = uBh[bi + 4];
                bl[ns][0] = uBl[bi];  bl[ns][1] = uBl[bi + 4];
            }
            #pragma unroll
            for (int ms = 0; ms < 2; ms++)
                #pragma unroll
                for (int ns = 0; ns < 4; ns++) {
                    mma_tf32(c[ms][ns], ah[ms], bh[ns]);   // hi*hi
                    mma_tf32(c[ms][ns], ah[ms], bl[ns]);   // hi*lo
                    mma_tf32(c[ms][ns], al[ms], bh[ns]);   // lo*hi
                }
        }
    }
}

// ---------------- kernel 1: fused QKV projections (tf32 MMA) -------------
// grid (8 n-tiles(=heads), 8 m-tiles of 128, 3 q/k/v), 256 threads.
__global__ void __launch_bounds__(256)
qkv_kernel(const float* __restrict__ x,
           const float* __restrict__ wq, const float* __restrict__ bq,
           const float* __restrict__ wk, const float* __restrict__ bk,
           const float* __restrict__ wv, const float* __restrict__ bv)
{
    __shared__ float Ah[128*TFS], Al[128*TFS], Bh[64*TFS], Bl[64*TFS];
    const int z = blockIdx.z;
    const float* W    = (z == 0) ? wq : (z == 1) ? wk : wv;
    const float* bias = (z == 0) ? bq : (z == 1) ? bk : bv;
    float* out        = (z == 0) ? g_q : (z == 1) ? g_k : g_v;
    const float scale = (z == 1) ? 0.125f : 1.0f;

    const int head = blockIdx.x;
    const int m0 = blockIdx.y * 128;
    const int n0 = head * 64;

    float c[2][4][4] = {};
    tf32_gemm_128x64(x, W, m0, n0, c, Ah, Al, Bh, Bl);

    const int tid = threadIdx.x, lane = tid & 31, wid = tid >> 5;
    const int mw = wid >> 1, nw = wid & 1;
    const int row = lane >> 2, qc = (lane & 3) << 1;
    #pragma unroll
    for (int ms = 0; ms < 2; ms++) {
        const int m = m0 + mw * 32 + ms * 16 + row;
        #pragma unroll
        for (int ns = 0; ns < 4; ns++) {
            const int nc = nw * 32 + ns * 8 + qc;    // head-local col
            const float b0 = bias[n0 + nc], b1 = bias[n0 + nc + 1];
            float2 o0 = make_float2((c[ms][ns][0] + b0) * scale,
                                    (c[ms][ns][1] + b1) * scale);
            float2 o1 = make_float2((c[ms][ns][2] + b0) * scale,
                                    (c[ms][ns][3] + b1) * scale);
            *(float2*)(out + (head * L + m    ) * HD + nc) = o0;
            *(float2*)(out + (head * L + m + 8) * HD + nc) = o1;
        }
    }
}

// ---------------- kernel 2: causal Toeplitz conv, balanced chunks --------
__global__ void __launch_bounds__(256)
conv_kernel(const float* __restrict__ phi)
{
    __shared__ float Ks[64*64];
    __shared__ float ph[128];
    int lb, ch;
    task_map(blockIdx.x, lb, ch);
    const int head = blockIdx.y;
    const int z    = blockIdx.z;
    const float* src = (z ? g_v : g_k) + head * L * HD;
    float* dst = g_cpart + (z * 4 + ch) * SZ + head * L * HD;

    const int tid = threadIdx.x;
    const int tx = tid & 15, ty = tid >> 4;
    const int l0 = lb * 64;
    const int sb_beg = ch * 4;
    const int sb_end = min(sb_beg + 4, lb + 1);
    float acc[4][4] = {};

    for (int sb = sb_beg; sb < sb_end; sb++) {
        const int s0 = sb * 64;
        #pragma unroll
        for (int rep = 0; rep < 4; rep++) {
            const int g  = tid + rep * 256;
            const int r  = g >> 4;
            const int c4 = (g & 15) << 2;
            *(float4*)(Ks + r*64 + c4) = *(const float4*)(src + (s0 + r) * HD + c4);
        }
        if (tid < 127) {
            const int off = l0 - s0 - 63 + tid;
            ph[tid] = (off >= 0) ? phi[off * H + head] : 0.0f;
        }
        __syncthreads();

        if (sb < lb) {
            #pragma unroll 4
            for (int s = 0; s < 64; s++) {
                float4 b4 = *(const float4*)(Ks + s*64 + (tx<<2));
                float b[4] = {b4.x, b4.y, b4.z, b4.w};
                #pragma unroll
                for (int i = 0; i < 4; i++) {
                    const float a = ph[63 + (ty<<2) + i - s];
                    #pragma unroll
                    for (int j = 0; j < 4; j++) acc[i][j] += a * b[j];
                }
            }
        } else {  // diagonal tile: causal mask l >= s
            #pragma unroll 4
            for (int s = 0; s < 64; s++) {
                float4 b4 = *(const float4*)(Ks + s*64 + (tx<<2));
                float b[4] = {b4.x, b4.y, b4.z, b4.w};
                #pragma unroll
                for (int i = 0; i < 4; i++) {
                    const int ll = (ty<<2) + i;
                    const float pv = ph[63 + ll - s];
                    const float a = (ll >= s) ? pv : 0.0f;
                    #pragma unroll
                    for (int j = 0; j < 4; j++) acc[i][j] += a * b[j];
                }
            }
        }
        __syncthreads();
    }

    #pragma unroll
    for (int i = 0; i < 4; i++) {
        float4 o = make_float4(acc[i][0], acc[i][1], acc[i][2], acc[i][3]);
        *(float4*)(dst + (l0 + (ty<<2) + i) * HD + (tx<<2)) = o;
    }
}

// ---------------- kernel 2b: conv finalize (sum <=4 partials) ------------
__global__ void __launch_bounds__(256)
conv_fin_kernel()
{
    const int z = blockIdx.y;
    const int f = blockIdx.x * 256 + threadIdx.x;
    const int flat = f << 2;
    const int l = (flat >> 6) & (L - 1);
    const int n = (l >> 8) + 1;
    const float* base = g_cpart + z * 4 * SZ;
    float4 s = ((const float4*)base)[f];
    for (int c = 1; c < n; c++) {
        float4 p = ((const float4*)(base + c * SZ))[f];
        s.x += p.x; s.y += p.y; s.z += p.z; s.w += p.w;
    }
    float* dst = z ? g_vc : g_kc;
    ((float4*)dst)[f] = s;
}

// ---------------- kernel 3: gates + per-tile state block T_j -------------
__global__ void __launch_bounds__(256)
gate_kernel(const float* __restrict__ wg, const float* __restrict__ wgb)
{
    __shared__ float sm[12288];
    float* KsT   = sm;
    float* wgT   = sm + 4096;
    float* Vcs   = sm + 8192;
    float* red   = sm;
    float* gvals = sm + 1536;

    const int lb = blockIdx.x, head = blockIdx.y;
    const int l0 = lb * 64;
    const float* kch = g_kc + (head * L + l0) * HD;
    const float* vch = g_vc + (head * L + l0) * HD;

    const int tid = threadIdx.x;
    const int tx = tid & 15, ty = tid >> 4;

    #pragma unroll
    for (int rep = 0; rep < 4; rep++) {
        const int g  = tid + rep * 256;
        const int r  = g >> 4;
        const int c4 = (g & 15) << 2;
        float4 kv = *(const float4*)(kch + r * HD + c4);
        KsT[(c4+0)*64 + r] = kv.x;
        KsT[(c4+1)*64 + r] = kv.y;
        KsT[(c4+2)*64 + r] = kv.z;
        KsT[(c4+3)*64 + r] = kv.w;
        *(float4*)(Vcs + r*64 + c4) = *(const float4*)(vch + r * HD + c4);
        float4 wv = *(const float4*)(wg + r * 64 + c4);
        wgT[(c4+0)*64 + r] = wv.x;
        wgT[(c4+1)*64 + r] = wv.y;
        wgT[(c4+2)*64 + r] = wv.z;
        wgT[(c4+3)*64 + r] = wv.w;
    }
    __syncthreads();

    float acc[4][4] = {};
    #pragma unroll 4
    for (int n = 0; n < 64; n++) {
        float4 a4 = *(const float4*)(KsT + n*64 + (ty<<2));
        float4 b4 = *(const float4*)(wgT + n*64 + (tx<<2));
        float a[4] = {a4.x, a4.y, a4.z, a4.w};
        float b[4] = {b4.x, b4.y, b4.z, b4.w};
        #pragma unroll
        for (int i = 0; i < 4; i++)
            #pragma unroll
            for (int j = 0; j < 4; j++)
                acc[i][j] += a[i] * b[j];
    }
    float psum[4];
    #pragma unroll
    for (int i = 0; i < 4; i++) {
        float4 v4 = *(const float4*)(Vcs + ((ty<<2)+i)*64 + (tx<<2));
        psum[i] = acc[i][0]*v4.x + acc[i][1]*v4.y + acc[i][2]*v4.z + acc[i][3]*v4.w;
    }
    __syncthreads();
    #pragma unroll
    for (int i = 0; i < 4; i++)
        red[((ty<<2)+i)*16 + tx] = psum[i];
    __syncthreads();

    if (tid < 64) {
        float s = 0.0f;
        #pragma unroll
        for (int t = 0; t < 16; t++) s += red[tid*16 + t];
        const float r = fmaxf(s + wgb[0], 0.0f);
        const float gv = r * r + EPSF;
        g_gate[head * L + l0 + tid] = gv;
        gvals[tid] = gv;
    }
    __syncthreads();

    float* Ksn = wgT;
    #pragma unroll
    for (int rep = 0; rep < 4; rep++) {
        const int g  = tid + rep * 256;
        const int r  = g >> 4;
        const int c4 = (g & 15) << 2;
        *(float4*)(Ksn + r*64 + c4) = *(const float4*)(kch + r * HD + c4);
    }
    #pragma unroll
    for (int k = 0; k < 4; k++) {
        const int f = tid + k * 256;
        const float gv = gvals[f >> 4];
        float4 v = ((float4*)Vcs)[f];
        v.x *= gv; v.y *= gv; v.z *= gv; v.w *= gv;
        ((float4*)Vcs)[f] = v;
    }
    __syncthreads();

    float tacc[4][4] = {};
    #pragma unroll 4
    for (int s = 0; s < 64; s++) {
        float4 a4 = *(const float4*)(Vcs + s*64 + (ty<<2));
        float4 b4 = *(const float4*)(Ksn + s*64 + (tx<<2));
        float a[4] = {a4.x, a4.y, a4.z, a4.w};
        float b[4] = {b4.x, b4.y, b4.z, b4.w};
        #pragma unroll
        for (int i = 0; i < 4; i++)
            #pragma unroll
            for (int j = 0; j < 4; j++)
                tacc[i][j] += a[i] * b[j];
    }
    float* dst = g_T + (head * 16 + lb) * 4096;
    #pragma unroll
    for (int i = 0; i < 4; i++)
        *(float4*)(dst + ((ty<<2)+i)*64 + (tx<<2)) =
            make_float4(tacc[i][0], tacc[i][1], tacc[i][2], tacc[i][3]);
}

// ---------------- kernel 4: inclusive prefix sum of gates per head -------
__global__ void __launch_bounds__(1024)
scan_kernel()
{
    __shared__ float s[L];
    const int head = blockIdx.x, t = threadIdx.x;
    s[t] = g_gate[head * L + t];
    __syncthreads();
    for (int off = 1; off < L; off <<= 1) {
        const float v = (t >= off) ? s[t - off] : 0.0f;
        __syncthreads();
        s[t] += v;
        __syncthreads();
    }
    g_gcum[head * L + t] = s[t];
}

// ---------------- kernel 5: chunked-state attention + normalize ----------
__global__ void __launch_bounds__(256)
ctxt_kernel()
{
    __shared__ float sm[12288];
    float* QsT = sm;
    float* Sb  = sm + 4096;
    float* Xb  = sm + 8192;

    const int j = blockIdx.x, head = blockIdx.y;
    const int l0 = j * 64;
    const float* qh  = g_q  + (head * L + l0) * HD;
    const float* kch = g_kc + (head * L + l0) * HD;
    const float* vch = g_vc + (head * L + l0) * HD;
    const float* gh  = g_gate + head * L + l0;

    const int tid = threadIdx.x;
    const int tx = tid & 15, ty = tid >> 4;

    #pragma unroll
    for (int rep = 0; rep < 4; rep++) {
        const int g  = tid + rep * 256;
        const int r  = g >> 4;
        const int c4 = (g & 15) << 2;
        float4 q4 = *(const float4*)(qh + r * HD + c4);
        QsT[(c4+0)*64 + r] = q4.x;
        QsT[(c4+1)*64 + r] = q4.y;
        QsT[(c4+2)*64 + r] = q4.z;
        QsT[(c4+3)*64 + r] = q4.w;
        const float gs = gh[r];
        float4 v4 = *(const float4*)(vch + r * HD + c4);
        Xb[(c4+0)*64 + r] = v4.x * gs;
        Xb[(c4+1)*64 + r] = v4.y * gs;
        Xb[(c4+2)*64 + r] = v4.z * gs;
        Xb[(c4+3)*64 + r] = v4.w * gs;
    }
    {
        float4 sacc0 = make_float4(0.f,0.f,0.f,0.f), sacc1 = sacc0,
               sacc2 = sacc0, sacc3 = sacc0;
        const float4* tbase = (const float4*)(g_T + head * 16 * 4096);
        for (int i = 0; i < j; i++) {
            const float4* tp = tbase + i * 1024;
            float4 p;
            p = tp[tid +   0]; sacc0.x += p.x; sacc0.y += p.y; sacc0.z += p.z; sacc0.w += p.w;
            p = tp[tid + 256]; sacc1.x += p.x; sacc1.y += p.y; sacc1.z += p.z; sacc1.w += p.w;
            p = tp[tid + 512]; sacc2.x += p.x; sacc2.y += p.y; sacc2.z += p.z; sacc2.w += p.w;
            p = tp[tid + 768]; sacc3.x += p.x; sacc3.y += p.y; sacc3.z += p.z; sacc3.w += p.w;
        }
        ((float4*)Sb)[tid +   0] = sacc0;
        ((float4*)Sb)[tid + 256] = sacc1;
        ((float4*)Sb)[tid + 512] = sacc2;
        ((float4*)Sb)[tid + 768] = sacc3;
    }
    __syncthreads();

    float acc[4][4] = {};
    if (j > 0) {
        #pragma unroll 4
        for (int d = 0; d < 64; d++) {
            float4 a4 = *(const float4*)(QsT + d*64 + (ty<<2));
            float4 b4 = *(const float4*)(Sb  + d*64 + (tx<<2));
            float a[4] = {a4.x, a4.y, a4.z, a4.w};
            float b[4] = {b4.x, b4.y, b4.z, b4.w};
            #pragma unroll
            for (int i = 0; i < 4; i++)
                #pragma unroll
                for (int jj = 0; jj < 4; jj++)
                    acc[i][jj] += a[i] * b[jj];
        }
    }

    float pacc[4][4] = {};
    #pragma unroll 4
    for (int d = 0; d < 64; d++) {
        float4 a4 = *(const float4*)(QsT + d*64 + (ty<<2));
        float4 b4 = *(const float4*)(Xb  + d*64 + (tx<<2));
        float a[4] = {a4.x, a4.y, a4.z, a4.w};
        float b[4] = {b4.x, b4.y, b4.z, b4.w};
        #pragma unroll
        for (int i = 0; i < 4; i++)
            #pragma unroll
            for (int jj = 0; jj < 4; jj++)
                pacc[i][jj] += a[i] * b[jj];
    }
    #pragma unroll
    for (int i = 0; i < 4; i++)
        #pragma unroll
        for (int jj = 0; jj < 4; jj++)
            if ((tx<<2) + jj > (ty<<2) + i) pacc[i][jj] = 0.0f;
    __syncthreads();

    #pragma unroll
    for (int i = 0; i < 4; i++)
        *(float4*)(Sb + ((ty<<2)+i)*64 + (tx<<2)) =
            make_float4(pacc[i][0], pacc[i][1], pacc[i][2], pacc[i][3]);
    #pragma unroll
    for (int rep = 0; rep < 4; rep++) {
        const int g  = tid + rep * 256;
        const int r  = g >> 4;
        const int c4 = (g & 15) << 2;
        *(float4*)(Xb + r*64 + c4) = *(const float4*)(kch + r * HD + c4);
    }
    __syncthreads();

    #pragma unroll 4
    for (int s = 0; s < 64; s++) {
        float a[4];
        #pragma unroll
        for (int i = 0; i < 4; i++) a[i] = Sb[((ty<<2)+i)*64 + s];
        float4 b4 = *(const float4*)(Xb + s*64 + (tx<<2));
        float b[4] = {b4.x, b4.y, b4.z, b4.w};
        #pragma unroll
        for (int i = 0; i < 4; i++)
            #pragma unroll
            for (int jj = 0; jj < 4; jj++)
                acc[i][jj] += a[i] * b[jj];
    }
    __syncthreads();

    #pragma unroll
    for (int i = 0; i < 4; i++) {
        const float G = g_gcum[head * L + l0 + (ty<<2) + i];
        const float gi = 1.0f / (G + EPSF);
        #pragma unroll
        for (int jj = 0; jj < 4; jj++) acc[i][jj] *= gi;
        *(float4*)(Sb + ((ty<<2)+i)*64 + (tx<<2)) =
            make_float4(acc[i][0], acc[i][1], acc[i][2], acc[i][3]);
    }
    __syncthreads();

    if (tid < 64) {
        float ss = 0.0f;
        #pragma unroll 8
        for (int d2 = 0; d2 < 64; d2++) {
            const float c = Sb[tid*64 + d2];
            ss += c * c;
        }
        Xb[tid] = fmaxf(sqrtf(ss), EPSF);
    }
    __syncthreads();

    #pragma unroll
    for (int i = 0; i < 4; i++) {
        const float ri = 1.0f / Xb[(ty<<2) + i];
        float4 o = make_float4(acc[i][0]*ri, acc[i][1]*ri, acc[i][2]*ri, acc[i][3]*ri);
        *(float4*)(g_unit + (l0 + (ty<<2) + i) * D + head * HD + (tx<<2)) = o;
    }
}

// ---------------- kernel 6: output projection (tf32 MMA) -----------------
// grid (8 n-tiles, 8 m-tiles of 128), 256 threads.
__global__ void __launch_bounds__(256)
oproj_kernel(const float* __restrict__ wo, const float* __restrict__ bo,
             float* __restrict__ out)
{
    __shared__ float Ah[128*TFS], Al[128*TFS], Bh[64*TFS], Bl[64*TFS];
    const int m0 = blockIdx.y * 128;
    const int n0 = blockIdx.x * 64;

    float c[2][4][4] = {};
    tf32_gemm_128x64(g_unit, wo, m0, n0, c, Ah, Al, Bh, Bl);

    const int tid = threadIdx.x, lane = tid & 31, wid = tid >> 5;
    const int mw = wid >> 1, nw = wid & 1;
    const int row = lane >> 2, qc = (lane & 3) << 1;
    #pragma unroll
    for (int ms = 0; ms < 2; ms++) {
        const int m = m0 + mw * 32 + ms * 16 + row;
        #pragma unroll
        for (int ns = 0; ns < 4; ns++) {
            const int nc = n0 + nw * 32 + ns * 8 + qc;
            const float b0 = bo[nc], b1 = bo[nc + 1];
            *(float2*)(out + m * D + nc) =
                make_float2(c[ms][ns][0] + b0, c[ms][ns][1] + b1);
            *(float2*)(out + (m + 8) * D + nc) =
                make_float2(c[ms][ns][2] + b0, c[ms][ns][3] + b1);
        }
    }
}

// ---------------- launch --------------------------------------------------
extern "C" void kernel_launch(void* const* d_in, const int* in_sizes, int n_in,
                              void* d_out, int out_size)
{
    const float* x   = (const float*)d_in[0];
    const float* phi = (const float*)d_in[1];
    const float* wq  = (const float*)d_in[2];
    const float* bq  = (const float*)d_in[3];
    const float* wk  = (const float*)d_in[4];
    const float* bk  = (const float*)d_in[5];
    const float* wv  = (const float*)d_in[6];
    const float* bv  = (const float*)d_in[7];
    const float* wo  = (const float*)d_in[8];
    const float* bo  = (const float*)d_in[9];
    const float* wg  = (const float*)d_in[10];
    const float* wgb = (const float*)d_in[11];
    float* out = (float*)d_out;

    qkv_kernel     <<<dim3(8, 8, 3), 256>>>(x, wq, bq, wk, bk, wv, bv);
    conv_kernel    <<<dim3(40, 8, 2), 256>>>(phi);
    conv_fin_kernel<<<dim3(512, 2), 256>>>();
    gate_kernel    <<<dim3(16, 8), 256>>>(wg, wgb);
    scan_kernel    <<<8, 1024>>>();
    ctxt_kernel    <<<dim3(16, 8), 256>>>();
    oproj_kernel   <<<dim3(8, 8), 256>>>(wo, bo, out);
}

// round 10
// speedup vs baseline: 1.3405x; 1.3405x over previous
#include <cuda_runtime.h>
#include <cstdint>

#define L   1024
#define D   512
#define H   8
#define HD  64
#define EPSF 1e-5f
#define SZ  (H*L*HD)          // 524288 elems per [H][L][HD] tensor

// ---------------- scratch (device globals; no allocation) ----------------
__device__ float g_q [SZ];
__device__ float g_k [SZ];
__device__ float g_v [SZ];
__device__ float g_kc[SZ];
__device__ float g_vc[SZ];
__device__ float g_gate[H*L];
__device__ float g_gcum[H*L];
__device__ float g_unit[L*D];
__device__ float g_cpart[2*4*SZ];   // conv partials: [z][chunk][H][L][HD]
__device__ float g_T[H*16*4096];    // per-tile state blocks T_j[m][n]

// Balanced triangular task map: 40 tasks per head, each <=4 s-tiles.
__device__ __forceinline__ void task_map(int t, int& lb, int& ch)
{
    int g, base;
    if      (t < 4)  { g = 0; base = 0;  }
    else if (t < 12) { g = 1; base = 4;  }
    else if (t < 24) { g = 2; base = 12; }
    else             { g = 3; base = 24; }
    const int idx = t - base;
    lb = g * 4 + idx / (g + 1);
    ch = idx % (g + 1);
}

// ================= single-pass tf32 MMA machinery ========================
__device__ __forceinline__ uint32_t f2tf32(float x)
{
    uint32_t r; asm("cvt.rna.tf32.f32 %0, %1;" : "=r"(r) : "f"(x)); return r;
}

__device__ __forceinline__ void mma_tf32(float c[4],
                                         const uint32_t a[4],
                                         const uint32_t b[2])
{
    asm("mma.sync.aligned.m16n8k8.row.col.f32.tf32.tf32.f32 "
        "{%0,%1,%2,%3}, {%4,%5,%6,%7}, {%8,%9}, {%0,%1,%2,%3};"
        : "+f"(c[0]), "+f"(c[1]), "+f"(c[2]), "+f"(c[3])
        : "r"(a[0]), "r"(a[1]), "r"(a[2]), "r"(a[3]),
          "r"(b[0]), "r"(b[1]));
}

// C[m][n] = sum_k A[m][k] * B[n][k]; block tile (64*MS)x64, K=512, 256 thr.
// Warps: 4(m) x 2(n); each m-warp covers MS m16-steps; 4 n8-steps per n-warp.
// smem stride 20 keeps fragment gathers bank-conflict-free.
#define TFS 20
template<int MS>
__device__ __forceinline__ void tf32_gemm(
    const float* __restrict__ A, const float* __restrict__ B,
    int m0, int n0, float c[MS][4][4],
    float* Ah, float* Bh)
{
    const int tid  = threadIdx.x;
    const int lane = tid & 31;
    const int wid  = tid >> 5;
    const int mw   = wid >> 1;          // 0..3
    const int nw   = wid & 1;           // 0..1
    const int row  = lane >> 2;         // 0..7
    const int kq   = lane & 3;          // 0..3

    const uint32_t* uAh = (const uint32_t*)Ah;
    const uint32_t* uBh = (const uint32_t*)Bh;

    for (int k0 = 0; k0 < 512; k0 += 16) {
        __syncthreads();
        // load A chunk: (64*MS) rows x 16 cols, cvt to tf32
        #pragma unroll
        for (int it = 0; it < MS; it++) {
            const int idx = tid + it * 256;
            const int r   = idx >> 2;
            const int c4  = (idx & 3) << 2;
            float4 g = *(const float4*)(A + (m0 + r) * 512 + k0 + c4);
            float4 hi4;
            hi4.x = __uint_as_float(f2tf32(g.x));
            hi4.y = __uint_as_float(f2tf32(g.y));
            hi4.z = __uint_as_float(f2tf32(g.z));
            hi4.w = __uint_as_float(f2tf32(g.w));
            *(float4*)(Ah + r * TFS + c4) = hi4;
        }
        // load B chunk: 64 rows x 16 cols
        {
            const int r  = tid >> 2;
            const int c4 = (tid & 3) << 2;
            float4 g = *(const float4*)(B + (n0 + r) * 512 + k0 + c4);
            float4 hi4;
            hi4.x = __uint_as_float(f2tf32(g.x));
            hi4.y = __uint_as_float(f2tf32(g.y));
            hi4.z = __uint_as_float(f2tf32(g.z));
            hi4.w = __uint_as_float(f2tf32(g.w));
            *(float4*)(Bh + r * TFS + c4) = hi4;
        }
        __syncthreads();

        #pragma unroll
        for (int k8 = 0; k8 < 16; k8 += 8) {
            uint32_t ah[MS][4], bh[4][2];
            #pragma unroll
            for (int ms = 0; ms < MS; ms++) {
                const int bi = (mw * (16 * MS) + ms * 16 + row) * TFS + k8 + kq;
                ah[ms][0] = uAh[bi];           ah[ms][1] = uAh[bi + 8*TFS];
                ah[ms][2] = uAh[bi + 4];       ah[ms][3] = uAh[bi + 8*TFS + 4];
            }
            #pragma unroll
            for (int ns = 0; ns < 4; ns++) {
                const int bi = (nw * 32 + ns * 8 + row) * TFS + k8 + kq;
                bh[ns][0] = uBh[bi];  bh[ns][1] = uBh[bi + 4];
            }
            #pragma unroll
            for (int ms = 0; ms < MS; ms++)
                #pragma unroll
                for (int ns = 0; ns < 4; ns++)
                    mma_tf32(c[ms][ns], ah[ms], bh[ns]);
        }
    }
}

// ---------------- kernel 1: fused QKV projections (tf32 MMA) -------------
// grid (8 heads, 8 m-tiles of 128, 3 q/k/v), 256 threads.
__global__ void __launch_bounds__(256)
qkv_kernel(const float* __restrict__ x,
           const float* __restrict__ wq, const float* __restrict__ bq,
           const float* __restrict__ wk, const float* __restrict__ bk,
           const float* __restrict__ wv, const float* __restrict__ bv)
{
    __shared__ float Ah[128*TFS], Bh[64*TFS];
    const int z = blockIdx.z;
    const float* W    = (z == 0) ? wq : (z == 1) ? wk : wv;
    const float* bias = (z == 0) ? bq : (z == 1) ? bk : bv;
    float* out        = (z == 0) ? g_q : (z == 1) ? g_k : g_v;
    const float scale = (z == 1) ? 0.125f : 1.0f;

    const int head = blockIdx.x;
    const int m0 = blockIdx.y * 128;
    const int n0 = head * 64;

    float c[2][4][4] = {};
    tf32_gemm<2>(x, W, m0, n0, c, Ah, Bh);

    const int tid = threadIdx.x, lane = tid & 31, wid = tid >> 5;
    const int mw = wid >> 1, nw = wid & 1;
    const int row = lane >> 2, qc = (lane & 3) << 1;
    #pragma unroll
    for (int ms = 0; ms < 2; ms++) {
        const int m = m0 + mw * 32 + ms * 16 + row;
        #pragma unroll
        for (int ns = 0; ns < 4; ns++) {
            const int nc = nw * 32 + ns * 8 + qc;    // head-local col
            const float b0 = bias[n0 + nc], b1 = bias[n0 + nc + 1];
            float2 o0 = make_float2((c[ms][ns][0] + b0) * scale,
                                    (c[ms][ns][1] + b1) * scale);
            float2 o1 = make_float2((c[ms][ns][2] + b0) * scale,
                                    (c[ms][ns][3] + b1) * scale);
            *(float2*)(out + (head * L + m    ) * HD + nc) = o0;
            *(float2*)(out + (head * L + m + 8) * HD + nc) = o1;
        }
    }
}

// ---------------- kernel 2: causal Toeplitz conv, balanced chunks --------
__global__ void __launch_bounds__(256)
conv_kernel(const float* __restrict__ phi)
{
    __shared__ float Ks[64*64];
    __shared__ float ph[128];
    int lb, ch;
    task_map(blockIdx.x, lb, ch);
    const int head = blockIdx.y;
    const int z    = blockIdx.z;
    const float* src = (z ? g_v : g_k) + head * L * HD;
    float* dst = g_cpart + (z * 4 + ch) * SZ + head * L * HD;

    const int tid = threadIdx.x;
    const int tx = tid & 15, ty = tid >> 4;
    const int l0 = lb * 64;
    const int sb_beg = ch * 4;
    const int sb_end = min(sb_beg + 4, lb + 1);
    float acc[4][4] = {};

    for (int sb = sb_beg; sb < sb_end; sb++) {
        const int s0 = sb * 64;
        #pragma unroll
        for (int rep = 0; rep < 4; rep++) {
            const int g  = tid + rep * 256;
            const int r  = g >> 4;
            const int c4 = (g & 15) << 2;
            *(float4*)(Ks + r*64 + c4) = *(const float4*)(src + (s0 + r) * HD + c4);
        }
        if (tid < 127) {
            const int off = l0 - s0 - 63 + tid;
            ph[tid] = (off >= 0) ? phi[off * H + head] : 0.0f;
        }
        __syncthreads();

        if (sb < lb) {
            #pragma unroll 4
            for (int s = 0; s < 64; s++) {
                float4 b4 = *(const float4*)(Ks + s*64 + (tx<<2));
                float b[4] = {b4.x, b4.y, b4.z, b4.w};
                #pragma unroll
                for (int i = 0; i < 4; i++) {
                    const float a = ph[63 + (ty<<2) + i - s];
                    #pragma unroll
                    for (int j = 0; j < 4; j++) acc[i][j] += a * b[j];
                }
            }
        } else {  // diagonal tile: causal mask l >= s
            #pragma unroll 4
            for (int s = 0; s < 64; s++) {
                float4 b4 = *(const float4*)(Ks + s*64 + (tx<<2));
                float b[4] = {b4.x, b4.y, b4.z, b4.w};
                #pragma unroll
                for (int i = 0; i < 4; i++) {
                    const int ll = (ty<<2) + i;
                    const float pv = ph[63 + ll - s];
                    const float a = (ll >= s) ? pv : 0.0f;
                    #pragma unroll
                    for (int j = 0; j < 4; j++) acc[i][j] += a * b[j];
                }
            }
        }
        __syncthreads();
    }

    #pragma unroll
    for (int i = 0; i < 4; i++) {
        float4 o = make_float4(acc[i][0], acc[i][1], acc[i][2], acc[i][3]);
        *(float4*)(dst + (l0 + (ty<<2) + i) * HD + (tx<<2)) = o;
    }
}

// ---------------- kernel 2b: conv finalize (sum <=4 partials) ------------
__global__ void __launch_bounds__(256)
conv_fin_kernel()
{
    const int z = blockIdx.y;
    const int f = blockIdx.x * 256 + threadIdx.x;
    const int flat = f << 2;
    const int l = (flat >> 6) & (L - 1);
    const int n = (l >> 8) + 1;
    const float* base = g_cpart + z * 4 * SZ;
    float4 s = ((const float4*)base)[f];
    for (int c = 1; c < n; c++) {
        float4 p = ((const float4*)(base + c * SZ))[f];
        s.x += p.x; s.y += p.y; s.z += p.z; s.w += p.w;
    }
    float* dst = z ? g_vc : g_kc;
    ((float4*)dst)[f] = s;
}

// ---------------- kernel 3: gates + per-tile state block T_j -------------
__global__ void __launch_bounds__(256)
gate_kernel(const float* __restrict__ wg, const float* __restrict__ wgb)
{
    __shared__ float sm[12288];
    float* KsT   = sm;
    float* wgT   = sm + 4096;
    float* Vcs   = sm + 8192;
    float* red   = sm;
    float* gvals = sm + 1536;

    const int lb = blockIdx.x, head = blockIdx.y;
    const int l0 = lb * 64;
    const float* kch = g_kc + (head * L + l0) * HD;
    const float* vch = g_vc + (head * L + l0) * HD;

    const int tid = threadIdx.x;
    const int tx = tid & 15, ty = tid >> 4;

    #pragma unroll
    for (int rep = 0; rep < 4; rep++) {
        const int g  = tid + rep * 256;
        const int r  = g >> 4;
        const int c4 = (g & 15) << 2;
        float4 kv = *(const float4*)(kch + r * HD + c4);
        KsT[(c4+0)*64 + r] = kv.x;
        KsT[(c4+1)*64 + r] = kv.y;
        KsT[(c4+2)*64 + r] = kv.z;
        KsT[(c4+3)*64 + r] = kv.w;
        *(float4*)(Vcs + r*64 + c4) = *(const float4*)(vch + r * HD + c4);
        float4 wv = *(const float4*)(wg + r * 64 + c4);
        wgT[(c4+0)*64 + r] = wv.x;
        wgT[(c4+1)*64 + r] = wv.y;
        wgT[(c4+2)*64 + r] = wv.z;
        wgT[(c4+3)*64 + r] = wv.w;
    }
    __syncthreads();

    float acc[4][4] = {};
    #pragma unroll 4
    for (int n = 0; n < 64; n++) {
        float4 a4 = *(const float4*)(KsT + n*64 + (ty<<2));
        float4 b4 = *(const float4*)(wgT + n*64 + (tx<<2));
        float a[4] = {a4.x, a4.y, a4.z, a4.w};
        float b[4] = {b4.x, b4.y, b4.z, b4.w};
        #pragma unroll
        for (int i = 0; i < 4; i++)
            #pragma unroll
            for (int j = 0; j < 4; j++)
                acc[i][j] += a[i] * b[j];
    }
    float psum[4];
    #pragma unroll
    for (int i = 0; i < 4; i++) {
        float4 v4 = *(const float4*)(Vcs + ((ty<<2)+i)*64 + (tx<<2));
        psum[i] = acc[i][0]*v4.x + acc[i][1]*v4.y + acc[i][2]*v4.z + acc[i][3]*v4.w;
    }
    __syncthreads();
    #pragma unroll
    for (int i = 0; i < 4; i++)
        red[((ty<<2)+i)*16 + tx] = psum[i];
    __syncthreads();

    if (tid < 64) {
        float s = 0.0f;
        #pragma unroll
        for (int t = 0; t < 16; t++) s += red[tid*16 + t];
        const float r = fmaxf(s + wgb[0], 0.0f);
        const float gv = r * r + EPSF;
        g_gate[head * L + l0 + tid] = gv;
        gvals[tid] = gv;
    }
    __syncthreads();

    float* Ksn = wgT;
    #pragma unroll
    for (int rep = 0; rep < 4; rep++) {
        const int g  = tid + rep * 256;
        const int r  = g >> 4;
        const int c4 = (g & 15) << 2;
        *(float4*)(Ksn + r*64 + c4) = *(const float4*)(kch + r * HD + c4);
    }
    #pragma unroll
    for (int k = 0; k < 4; k++) {
        const int f = tid + k * 256;
        const float gv = gvals[f >> 4];
        float4 v = ((float4*)Vcs)[f];
        v.x *= gv; v.y *= gv; v.z *= gv; v.w *= gv;
        ((float4*)Vcs)[f] = v;
    }
    __syncthreads();

    float tacc[4][4] = {};
    #pragma unroll 4
    for (int s = 0; s < 64; s++) {
        float4 a4 = *(const float4*)(Vcs + s*64 + (ty<<2));
        float4 b4 = *(const float4*)(Ksn + s*64 + (tx<<2));
        float a[4] = {a4.x, a4.y, a4.z, a4.w};
        float b[4] = {b4.x, b4.y, b4.z, b4.w};
        #pragma unroll
        for (int i = 0; i < 4; i++)
            #pragma unroll
            for (int j = 0; j < 4; j++)
                tacc[i][j] += a[i] * b[j];
    }
    float* dst = g_T + (head * 16 + lb) * 4096;
    #pragma unroll
    for (int i = 0; i < 4; i++)
        *(float4*)(dst + ((ty<<2)+i)*64 + (tx<<2)) =
            make_float4(tacc[i][0], tacc[i][1], tacc[i][2], tacc[i][3]);
}

// ---------------- kernel 4: inclusive prefix sum of gates per head -------
__global__ void __launch_bounds__(1024)
scan_kernel()
{
    __shared__ float s[L];
    const int head = blockIdx.x, t = threadIdx.x;
    s[t] = g_gate[head * L + t];
    __syncthreads();
    for (int off = 1; off < L; off <<= 1) {
        const float v = (t >= off) ? s[t - off] : 0.0f;
        __syncthreads();
        s[t] += v;
        __syncthreads();
    }
    g_gcum[head * L + t] = s[t];
}

// ---------------- kernel 5: chunked-state attention + normalize ----------
__global__ void __launch_bounds__(256)
ctxt_kernel()
{
    __shared__ float sm[12288];
    float* QsT = sm;
    float* Sb  = sm + 4096;
    float* Xb  = sm + 8192;

    const int j = blockIdx.x, head = blockIdx.y;
    const int l0 = j * 64;
    const float* qh  = g_q  + (head * L + l0) * HD;
    const float* kch = g_kc + (head * L + l0) * HD;
    const float* vch = g_vc + (head * L + l0) * HD;
    const float* gh  = g_gate + head * L + l0;

    const int tid = threadIdx.x;
    const int tx = tid & 15, ty = tid >> 4;

    #pragma unroll
    for (int rep = 0; rep < 4; rep++) {
        const int g  = tid + rep * 256;
        const int r  = g >> 4;
        const int c4 = (g & 15) << 2;
        float4 q4 = *(const float4*)(qh + r * HD + c4);
        QsT[(c4+0)*64 + r] = q4.x;
        QsT[(c4+1)*64 + r] = q4.y;
        QsT[(c4+2)*64 + r] = q4.z;
        QsT[(c4+3)*64 + r] = q4.w;
        const float gs = gh[r];
        float4 v4 = *(const float4*)(vch + r * HD + c4);
        Xb[(c4+0)*64 + r] = v4.x * gs;
        Xb[(c4+1)*64 + r] = v4.y * gs;
        Xb[(c4+2)*64 + r] = v4.z * gs;
        Xb[(c4+3)*64 + r] = v4.w * gs;
    }
    {
        float4 sacc0 = make_float4(0.f,0.f,0.f,0.f), sacc1 = sacc0,
               sacc2 = sacc0, sacc3 = sacc0;
        const float4* tbase = (const float4*)(g_T + head * 16 * 4096);
        for (int i = 0; i < j; i++) {
            const float4* tp = tbase + i * 1024;
            float4 p;
            p = tp[tid +   0]; sacc0.x += p.x; sacc0.y += p.y; sacc0.z += p.z; sacc0.w += p.w;
            p = tp[tid + 256]; sacc1.x += p.x; sacc1.y += p.y; sacc1.z += p.z; sacc1.w += p.w;
            p = tp[tid + 512]; sacc2.x += p.x; sacc2.y += p.y; sacc2.z += p.z; sacc2.w += p.w;
            p = tp[tid + 768]; sacc3.x += p.x; sacc3.y += p.y; sacc3.z += p.z; sacc3.w += p.w;
        }
        ((float4*)Sb)[tid +   0] = sacc0;
        ((float4*)Sb)[tid + 256] = sacc1;
        ((float4*)Sb)[tid + 512] = sacc2;
        ((float4*)Sb)[tid + 768] = sacc3;
    }
    __syncthreads();

    float acc[4][4] = {};
    if (j > 0) {
        #pragma unroll 4
        for (int d = 0; d < 64; d++) {
            float4 a4 = *(const float4*)(QsT + d*64 + (ty<<2));
            float4 b4 = *(const float4*)(Sb  + d*64 + (tx<<2));
            float a[4] = {a4.x, a4.y, a4.z, a4.w};
            float b[4] = {b4.x, b4.y, b4.z, b4.w};
            #pragma unroll
            for (int i = 0; i < 4; i++)
                #pragma unroll
                for (int jj = 0; jj < 4; jj++)
                    acc[i][jj] += a[i] * b[jj];
        }
    }

    float pacc[4][4] = {};
    #pragma unroll 4
    for (int d = 0; d < 64; d++) {
        float4 a4 = *(const float4*)(QsT + d*64 + (ty<<2));
        float4 b4 = *(const float4*)(Xb  + d*64 + (tx<<2));
        float a[4] = {a4.x, a4.y, a4.z, a4.w};
        float b[4] = {b4.x, b4.y, b4.z, b4.w};
        #pragma unroll
        for (int i = 0; i < 4; i++)
            #pragma unroll
            for (int jj = 0; jj < 4; jj++)
                pacc[i][jj] += a[i] * b[jj];
    }
    #pragma unroll
    for (int i = 0; i < 4; i++)
        #pragma unroll
        for (int jj = 0; jj < 4; jj++)
            if ((tx<<2) + jj > (ty<<2) + i) pacc[i][jj] = 0.0f;
    __syncthreads();

    #pragma unroll
    for (int i = 0; i < 4; i++)
        *(float4*)(Sb + ((ty<<2)+i)*64 + (tx<<2)) =
            make_float4(pacc[i][0], pacc[i][1], pacc[i][2], pacc[i][3]);
    #pragma unroll
    for (int rep = 0; rep < 4; rep++) {
        const int g  = tid + rep * 256;
        const int r  = g >> 4;
        const int c4 = (g & 15) << 2;
        *(float4*)(Xb + r*64 + c4) = *(const float4*)(kch + r * HD + c4);
    }
    __syncthreads();

    #pragma unroll 4
    for (int s = 0; s < 64; s++) {
        float a[4];
        #pragma unroll
        for (int i = 0; i < 4; i++) a[i] = Sb[((ty<<2)+i)*64 + s];
        float4 b4 = *(const float4*)(Xb + s*64 + (tx<<2));
        float b[4] = {b4.x, b4.y, b4.z, b4.w};
        #pragma unroll
        for (int i = 0; i < 4; i++)
            #pragma unroll
            for (int jj = 0; jj < 4; jj++)
                acc[i][jj] += a[i] * b[jj];
    }
    __syncthreads();

    #pragma unroll
    for (int i = 0; i < 4; i++) {
        const float G = g_gcum[head * L + l0 + (ty<<2) + i];
        const float gi = 1.0f / (G + EPSF);
        #pragma unroll
        for (int jj = 0; jj < 4; jj++) acc[i][jj] *= gi;
        *(float4*)(Sb + ((ty<<2)+i)*64 + (tx<<2)) =
            make_float4(acc[i][0], acc[i][1], acc[i][2], acc[i][3]);
    }
    __syncthreads();

    if (tid < 64) {
        float ss = 0.0f;
        #pragma unroll 8
        for (int d2 = 0; d2 < 64; d2++) {
            const float c = Sb[tid*64 + d2];
            ss += c * c;
        }
        Xb[tid] = fmaxf(sqrtf(ss), EPSF);
    }
    __syncthreads();

    #pragma unroll
    for (int i = 0; i < 4; i++) {
        const float ri = 1.0f / Xb[(ty<<2) + i];
        float4 o = make_float4(acc[i][0]*ri, acc[i][1]*ri, acc[i][2]*ri, acc[i][3]*ri);
        *(float4*)(g_unit + (l0 + (ty<<2) + i) * D + head * HD + (tx<<2)) = o;
    }
}

// ---------------- kernel 6: output projection (tf32 MMA, 64x64 tiles) ----
// grid (8 n-tiles, 16 m-tiles of 64), 256 threads.
__global__ void __launch_bounds__(256)
oproj_kernel(const float* __restrict__ wo, const float* __restrict__ bo,
             float* __restrict__ out)
{
    __shared__ float Ah[64*TFS], Bh[64*TFS];
    const int m0 = blockIdx.y * 64;
    const int n0 = blockIdx.x * 64;

    float c[1][4][4] = {};
    tf32_gemm<1>(g_unit, wo, m0, n0, c, Ah, Bh);

    const int tid = threadIdx.x, lane = tid & 31, wid = tid >> 5;
    const int mw = wid >> 1, nw = wid & 1;
    const int row = lane >> 2, qc = (lane & 3) << 1;
    const int m = m0 + mw * 16 + row;
    #pragma unroll
    for (int ns = 0; ns < 4; ns++) {
        const int nc = n0 + nw * 32 + ns * 8 + qc;
        const float b0 = bo[nc], b1 = bo[nc + 1];
        *(float2*)(out + m * D + nc) =
            make_float2(c[0][ns][0] + b0, c[0][ns][1] + b1);
        *(float2*)(out + (m + 8) * D + nc) =
            make_float2(c[0][ns][2] + b0, c[0][ns][3] + b1);
    }
}

// ---------------- launch --------------------------------------------------
extern "C" void kernel_launch(void* const* d_in, const int* in_sizes, int n_in,
                              void* d_out, int out_size)
{
    const float* x   = (const float*)d_in[0];
    const float* phi = (const float*)d_in[1];
    const float* wq  = (const float*)d_in[2];
    const float* bq  = (const float*)d_in[3];
    const float* wk  = (const float*)d_in[4];
    const float* bk  = (const float*)d_in[5];
    const float* wv  = (const float*)d_in[6];
    const float* bv  = (const float*)d_in[7];
    const float* wo  = (const float*)d_in[8];
    const float* bo  = (const float*)d_in[9];
    const float* wg  = (const float*)d_in[10];
    const float* wgb = (const float*)d_in[11];
    float* out = (float*)d_out;

    qkv_kernel     <<<dim3(8, 8, 3), 256>>>(x, wq, bq, wk, bk, wv, bv);
    conv_kernel    <<<dim3(40, 8, 2), 256>>>(phi);
    conv_fin_kernel<<<dim3(512, 2), 256>>>();
    gate_kernel    <<<dim3(16, 8), 256>>>(wg, wgb);
    scan_kernel    <<<8, 1024>>>();
    ctxt_kernel    <<<dim3(16, 8), 256>>>();
    oproj_kernel   <<<dim3(8, 16), 256>>>(wo, bo, out);
}

// round 12
// speedup vs baseline: 1.3443x; 1.0028x over previous
#include <cuda_runtime.h>
#include <cstdint>

#define L   1024
#define D   512
#define H   8
#define HD  64
#define EPSF 1e-5f
#define SZ  (H*L*HD)          // 524288 elems per [H][L][HD] tensor

// ---------------- scratch (device globals; no allocation) ----------------
__device__ float g_q [SZ];
__device__ float g_k [SZ];
__device__ float g_v [SZ];
__device__ float g_kc[SZ];
__device__ float g_vc[SZ];
__device__ float g_gate[H*L];
__device__ float g_unit[L*D];
__device__ float g_cpart[2*4*SZ];   // conv partials: [z][chunk][H][L][HD]
__device__ float g_T[H*16*4096];    // per-tile state blocks T_j[m][n]

// Balanced triangular task map: 40 tasks per head, each <=4 s-tiles.
__device__ __forceinline__ void task_map(int t, int& lb, int& ch)
{
    int g, base;
    if      (t < 4)  { g = 0; base = 0;  }
    else if (t < 12) { g = 1; base = 4;  }
    else if (t < 24) { g = 2; base = 12; }
    else             { g = 3; base = 24; }
    const int idx = t - base;
    lb = g * 4 + idx / (g + 1);
    ch = idx % (g + 1);
}

// ================= single-pass tf32 MMA machinery ========================
__device__ __forceinline__ uint32_t f2tf32(float x)
{
    uint32_t r; asm("cvt.rna.tf32.f32 %0, %1;" : "=r"(r) : "f"(x)); return r;
}

__device__ __forceinline__ void mma_tf32(float c[4],
                                         const uint32_t a[4],
                                         const uint32_t b[2])
{
    asm("mma.sync.aligned.m16n8k8.row.col.f32.tf32.tf32.f32 "
        "{%0,%1,%2,%3}, {%4,%5,%6,%7}, {%8,%9}, {%0,%1,%2,%3};"
        : "+f"(c[0]), "+f"(c[1]), "+f"(c[2]), "+f"(c[3])
        : "r"(a[0]), "r"(a[1]), "r"(a[2]), "r"(a[3]),
          "r"(b[0]), "r"(b[1]));
}

// C[m][n] = sum_k A[m][k] * B[n][k]; block tile (64*MS)x64, K=512, 256 thr.
#define TFS 20
template<int MS>
__device__ __forceinline__ void tf32_gemm(
    const float* __restrict__ A, const float* __restrict__ B,
    int m0, int n0, float c[MS][4][4],
    float* Ah, float* Bh)
{
    const int tid  = threadIdx.x;
    const int lane = tid & 31;
    const int wid  = tid >> 5;
    const int mw   = wid >> 1;
    const int nw   = wid & 1;
    const int row  = lane >> 2;
    const int kq   = lane & 3;

    const uint32_t* uAh = (const uint32_t*)Ah;
    const uint32_t* uBh = (const uint32_t*)Bh;

    for (int k0 = 0; k0 < 512; k0 += 16) {
        __syncthreads();
        #pragma unroll
        for (int it = 0; it < MS; it++) {
            const int idx = tid + it * 256;
            const int r   = idx >> 2;
            const int c4  = (idx & 3) << 2;
            float4 g = *(const float4*)(A + (m0 + r) * 512 + k0 + c4);
            float4 hi4;
            hi4.x = __uint_as_float(f2tf32(g.x));
            hi4.y = __uint_as_float(f2tf32(g.y));
            hi4.z = __uint_as_float(f2tf32(g.z));
            hi4.w = __uint_as_float(f2tf32(g.w));
            *(float4*)(Ah + r * TFS + c4) = hi4;
        }
        {
            const int r  = tid >> 2;
            const int c4 = (tid & 3) << 2;
            float4 g = *(const float4*)(B + (n0 + r) * 512 + k0 + c4);
            float4 hi4;
            hi4.x = __uint_as_float(f2tf32(g.x));
            hi4.y = __uint_as_float(f2tf32(g.y));
            hi4.z = __uint_as_float(f2tf32(g.z));
            hi4.w = __uint_as_float(f2tf32(g.w));
            *(float4*)(Bh + r * TFS + c4) = hi4;
        }
        __syncthreads();

        #pragma unroll
        for (int k8 = 0; k8 < 16; k8 += 8) {
            uint32_t ah[MS][4], bh[4][2];
            #pragma unroll
            for (int ms = 0; ms < MS; ms++) {
                const int bi = (mw * (16 * MS) + ms * 16 + row) * TFS + k8 + kq;
                ah[ms][0] = uAh[bi];           ah[ms][1] = uAh[bi + 8*TFS];
                ah[ms][2] = uAh[bi + 4];       ah[ms][3] = uAh[bi + 8*TFS + 4];
            }
            #pragma unroll
            for (int ns = 0; ns < 4; ns++) {
                const int bi = (nw * 32 + ns * 8 + row) * TFS + k8 + kq;
                bh[ns][0] = uBh[bi];  bh[ns][1] = uBh[bi + 4];
            }
            #pragma unroll
            for (int ms = 0; ms < MS; ms++)
                #pragma unroll
                for (int ns = 0; ns < 4; ns++)
                    mma_tf32(c[ms][ns], ah[ms], bh[ns]);
        }
    }
}

// ---------------- kernel 1: fused QKV projections (tf32 MMA) -------------
__global__ void __launch_bounds__(256)
qkv_kernel(const float* __restrict__ x,
           const float* __restrict__ wq, const float* __restrict__ bq,
           const float* __restrict__ wk, const float* __restrict__ bk,
           const float* __restrict__ wv, const float* __restrict__ bv)
{
    __shared__ float Ah[128*TFS], Bh[64*TFS];
    const int z = blockIdx.z;
    const float* W    = (z == 0) ? wq : (z == 1) ? wk : wv;
    const float* bias = (z == 0) ? bq : (z == 1) ? bk : bv;
    float* out        = (z == 0) ? g_q : (z == 1) ? g_k : g_v;
    const float scale = (z == 1) ? 0.125f : 1.0f;

    const int head = blockIdx.x;
    const int m0 = blockIdx.y * 128;
    const int n0 = head * 64;

    float c[2][4][4] = {};
    tf32_gemm<2>(x, W, m0, n0, c, Ah, Bh);

    const int tid = threadIdx.x, lane = tid & 31, wid = tid >> 5;
    const int mw = wid >> 1, nw = wid & 1;
    const int row = lane >> 2, qc = (lane & 3) << 1;
    #pragma unroll
    for (int ms = 0; ms < 2; ms++) {
        const int m = m0 + mw * 32 + ms * 16 + row;
        #pragma unroll
        for (int ns = 0; ns < 4; ns++) {
            const int nc = nw * 32 + ns * 8 + qc;
            const float b0 = bias[n0 + nc], b1 = bias[n0 + nc + 1];
            float2 o0 = make_float2((c[ms][ns][0] + b0) * scale,
                                    (c[ms][ns][1] + b1) * scale);
            float2 o1 = make_float2((c[ms][ns][2] + b0) * scale,
                                    (c[ms][ns][3] + b1) * scale);
            *(float2*)(out + (head * L + m    ) * HD + nc) = o0;
            *(float2*)(out + (head * L + m + 8) * HD + nc) = o1;
        }
    }
}

// ---------------- kernel 2: causal Toeplitz conv, balanced chunks --------
__global__ void __launch_bounds__(256)
conv_kernel(const float* __restrict__ phi)
{
    __shared__ float Ks[64*64];
    __shared__ float ph[128];
    int lb, ch;
    task_map(blockIdx.x, lb, ch);
    const int head = blockIdx.y;
    const int z    = blockIdx.z;
    const float* src = (z ? g_v : g_k) + head * L * HD;
    float* dst = g_cpart + (z * 4 + ch) * SZ + head * L * HD;

    const int tid = threadIdx.x;
    const int tx = tid & 15, ty = tid >> 4;
    const int l0 = lb * 64;
    const int sb_beg = ch * 4;
    const int sb_end = min(sb_beg + 4, lb + 1);
    float acc[4][4] = {};

    for (int sb = sb_beg; sb < sb_end; sb++) {
        const int s0 = sb * 64;
        #pragma unroll
        for (int rep = 0; rep < 4; rep++) {
            const int g  = tid + rep * 256;
            const int r  = g >> 4;
            const int c4 = (g & 15) << 2;
            *(float4*)(Ks + r*64 + c4) = *(const float4*)(src + (s0 + r) * HD + c4);
        }
        if (tid < 127) {
            const int off = l0 - s0 - 63 + tid;
            ph[tid] = (off >= 0) ? phi[off * H + head] : 0.0f;
        }
        __syncthreads();

        if (sb < lb) {
            #pragma unroll 4
            for (int s = 0; s < 64; s++) {
                float4 b4 = *(const float4*)(Ks + s*64 + (tx<<2));
                float b[4] = {b4.x, b4.y, b4.z, b4.w};
                #pragma unroll
                for (int i = 0; i < 4; i++) {
                    const float a = ph[63 + (ty<<2) + i - s];
                    #pragma unroll
                    for (int j = 0; j < 4; j++) acc[i][j] += a * b[j];
                }
            }
        } else {  // diagonal tile: causal mask l >= s
            #pragma unroll 4
            for (int s = 0; s < 64; s++) {
                float4 b4 = *(const float4*)(Ks + s*64 + (tx<<2));
                float b[4] = {b4.x, b4.y, b4.z, b4.w};
                #pragma unroll
                for (int i = 0; i < 4; i++) {
                    const int ll = (ty<<2) + i;
                    const float pv = ph[63 + ll - s];
                    const float a = (ll >= s) ? pv : 0.0f;
                    #pragma unroll
                    for (int j = 0; j < 4; j++) acc[i][j] += a * b[j];
                }
            }
        }
        __syncthreads();
    }

    #pragma unroll
    for (int i = 0; i < 4; i++) {
        float4 o = make_float4(acc[i][0], acc[i][1], acc[i][2], acc[i][3]);
        *(float4*)(dst + (l0 + (ty<<2) + i) * HD + (tx<<2)) = o;
    }
}

// ---------------- kernel 3: conv-finalize + gates + state block T_j ------
__global__ void __launch_bounds__(256)
gate_kernel(const float* __restrict__ wg, const float* __restrict__ wgb)
{
    __shared__ float sm[12288];
    float* KsT   = sm;                  // [n][l] finalized Kc transposed
    float* wgT   = sm + 4096;           // [n][m]; phase B: Ksn [s][n]
    float* Vcs   = sm + 8192;           // [s][m] finalized Vc
    float* red   = sm;                  // alias after phase A reads
    float* gvals = sm + 1536;

    const int lb = blockIdx.x, head = blockIdx.y;
    const int l0 = lb * 64;
    const int nchunks = (lb >> 2) + 1;
    const float* kp = g_cpart + head * L * HD + l0 * HD;            // z=0,ch=0
    const float* vp = g_cpart + 4 * SZ + head * L * HD + l0 * HD;   // z=1,ch=0

    const int tid = threadIdx.x;
    const int tx = tid & 15, ty = tid >> 4;

    // finalize conv partials for this tile (same c-order as old conv_fin),
    // write to g_kc/g_vc and stage into smem
    #pragma unroll
    for (int rep = 0; rep < 4; rep++) {
        const int g  = tid + rep * 256;
        const int r  = g >> 4;
        const int c4 = (g & 15) << 2;
        const int off = r * HD + c4;

        float4 kv = *(const float4*)(kp + off);
        for (int c = 1; c < nchunks; c++) {
            float4 p = *(const float4*)(kp + c * SZ + off);
            kv.x += p.x; kv.y += p.y; kv.z += p.z; kv.w += p.w;
        }
        *(float4*)(g_kc + (head * L + l0 + r) * HD + c4) = kv;
        KsT[(c4+0)*64 + r] = kv.x;
        KsT[(c4+1)*64 + r] = kv.y;
        KsT[(c4+2)*64 + r] = kv.z;
        KsT[(c4+3)*64 + r] = kv.w;

        float4 vv = *(const float4*)(vp + off);
        for (int c = 1; c < nchunks; c++) {
            float4 p = *(const float4*)(vp + c * SZ + off);
            vv.x += p.x; vv.y += p.y; vv.z += p.z; vv.w += p.w;
        }
        *(float4*)(g_vc + (head * L + l0 + r) * HD + c4) = vv;
        *(float4*)(Vcs + r*64 + c4) = vv;

        float4 wv = *(const float4*)(wg + r * 64 + c4);
        wgT[(c4+0)*64 + r] = wv.x;
        wgT[(c4+1)*64 + r] = wv.y;
        wgT[(c4+2)*64 + r] = wv.z;
        wgT[(c4+3)*64 + r] = wv.w;
    }
    __syncthreads();

    // Phase A: Tg[l][m] = sum_n kc[l,n]*W[m,n]; psum = <Tg[l], vc[l]>
    float acc[4][4] = {};
    #pragma unroll 4
    for (int n = 0; n < 64; n++) {
        float4 a4 = *(const float4*)(KsT + n*64 + (ty<<2));
        float4 b4 = *(const float4*)(wgT + n*64 + (tx<<2));
        float a[4] = {a4.x, a4.y, a4.z, a4.w};
        float b[4] = {b4.x, b4.y, b4.z, b4.w};
        #pragma unroll
        for (int i = 0; i < 4; i++)
            #pragma unroll
            for (int j = 0; j < 4; j++)
                acc[i][j] += a[i] * b[j];
    }
    float psum[4];
    #pragma unroll
    for (int i = 0; i < 4; i++) {
        float4 v4 = *(const float4*)(Vcs + ((ty<<2)+i)*64 + (tx<<2));
        psum[i] = acc[i][0]*v4.x + acc[i][1]*v4.y + acc[i][2]*v4.z + acc[i][3]*v4.w;
    }
    __syncthreads();
    #pragma unroll
    for (int i = 0; i < 4; i++)
        red[((ty<<2)+i)*16 + tx] = psum[i];
    __syncthreads();

    if (tid < 64) {
        float s = 0.0f;
        #pragma unroll
        for (int t = 0; t < 16; t++) s += red[tid*16 + t];
        const float r = fmaxf(s + wgb[0], 0.0f);
        const float gv = r * r + EPSF;
        g_gate[head * L + l0 + tid] = gv;
        gvals[tid] = gv;
    }
    __syncthreads();

    // Phase B: reload own finalized Kc (L1-hot) natural into wgT area
    float* Ksn = wgT;
    const float* kch = g_kc + (head * L + l0) * HD;
    #pragma unroll
    for (int rep = 0; rep < 4; rep++) {
        const int g  = tid + rep * 256;
        const int r  = g >> 4;
        const int c4 = (g & 15) << 2;
        *(float4*)(Ksn + r*64 + c4) = *(const float4*)(kch + r * HD + c4);
    }
    #pragma unroll
    for (int k = 0; k < 4; k++) {
        const int f = tid + k * 256;
        const float gv = gvals[f >> 4];
        float4 v = ((float4*)Vcs)[f];
        v.x *= gv; v.y *= gv; v.z *= gv; v.w *= gv;
        ((float4*)Vcs)[f] = v;
    }
    __syncthreads();

    float tacc[4][4] = {};
    #pragma unroll 4
    for (int s = 0; s < 64; s++) {
        float4 a4 = *(const float4*)(Vcs + s*64 + (ty<<2));
        float4 b4 = *(const float4*)(Ksn + s*64 + (tx<<2));
        float a[4] = {a4.x, a4.y, a4.z, a4.w};
        float b[4] = {b4.x, b4.y, b4.z, b4.w};
        #pragma unroll
        for (int i = 0; i < 4; i++)
            #pragma unroll
            for (int j = 0; j < 4; j++)
                tacc[i][j] += a[i] * b[j];
    }
    float* dst = g_T + (head * 16 + lb) * 4096;
    #pragma unroll
    for (int i = 0; i < 4; i++)
        *(float4*)(dst + ((ty<<2)+i)*64 + (tx<<2)) =
            make_float4(tacc[i][0], tacc[i][1], tacc[i][2], tacc[i][3]);
}

// ---------------- kernel 4: gate scan + chunked-state attention ----------
__global__ void __launch_bounds__(256)
ctxt_kernel()
{
    __shared__ float sm[12288];
    float* QsT = sm;
    float* Sb  = sm + 4096;
    float* Xb  = sm + 8192;

    const int j = blockIdx.x, head = blockIdx.y;
    const int l0 = j * 64;
    const float* qh  = g_q  + (head * L + l0) * HD;
    const float* kch = g_kc + (head * L + l0) * HD;
    const float* vch = g_vc + (head * L + l0) * HD;
    const float* gh  = g_gate + head * L + l0;

    const int tid = threadIdx.x;
    const int tx = tid & 15, ty = tid >> 4;

    // fused inclusive prefix-scan of this head's 1024 gates
    float Greg[4];
    {
        const float* gfull = g_gate + head * L;
        float4 gv = *(const float4*)(gfull + tid * 4);
        const float p0 = gv.x;
        const float p1 = p0 + gv.y;
        const float p2 = p1 + gv.z;
        const float p3 = p2 + gv.w;
        Sb[tid] = p3;
        __syncthreads();
        for (int off = 1; off < 256; off <<= 1) {
            const float v = (tid >= off) ? Sb[tid - off] : 0.0f;
            __syncthreads();
            Sb[tid] += v;
            __syncthreads();
        }
        const float excl = Sb[tid] - p3;
        const int e0 = tid * 4;
        if (e0 >= l0 && e0 < l0 + 64) {
            Xb[e0 - l0 + 0] = excl + p0;
            Xb[e0 - l0 + 1] = excl + p1;
            Xb[e0 - l0 + 2] = excl + p2;
            Xb[e0 - l0 + 3] = excl + p3;
        }
        __syncthreads();
        #pragma unroll
        for (int i = 0; i < 4; i++) Greg[i] = Xb[(ty<<2) + i];
        __syncthreads();
    }

    #pragma unroll
    for (int rep = 0; rep < 4; rep++) {
        const int g  = tid + rep * 256;
        const int r  = g >> 4;
        const int c4 = (g & 15) << 2;
        float4 q4 = *(const float4*)(qh + r * HD + c4);
        QsT[(c4+0)*64 + r] = q4.x;
        QsT[(c4+1)*64 + r] = q4.y;
        QsT[(c4+2)*64 + r] = q4.z;
        QsT[(c4+3)*64 + r] = q4.w;
        const float gs = gh[r];
        float4 v4 = *(const float4*)(vch + r * HD + c4);
        Xb[(c4+0)*64 + r] = v4.x * gs;
        Xb[(c4+1)*64 + r] = v4.y * gs;
        Xb[(c4+2)*64 + r] = v4.z * gs;
        Xb[(c4+3)*64 + r] = v4.w * gs;
    }
    {
        float4 sacc0 = make_float4(0.f,0.f,0.f,0.f), sacc1 = sacc0,
               sacc2 = sacc0, sacc3 = sacc0;
        const float4* tbase = (const float4*)(g_T + head * 16 * 4096);
        for (int i = 0; i < j; i++) {
            const float4* tp = tbase + i * 1024;
            float4 p;
            p = tp[tid +   0]; sacc0.x += p.x; sacc0.y += p.y; sacc0.z += p.z; sacc0.w += p.w;
            p = tp[tid + 256]; sacc1.x += p.x; sacc1.y += p.y; sacc1.z += p.z; sacc1.w += p.w;
            p = tp[tid + 512]; sacc2.x += p.x; sacc2.y += p.y; sacc2.z += p.z; sacc2.w += p.w;
            p = tp[tid + 768]; sacc3.x += p.x; sacc3.y += p.y; sacc3.z += p.z; sacc3.w += p.w;
        }
        ((float4*)Sb)[tid +   0] = sacc0;
        ((float4*)Sb)[tid + 256] = sacc1;
        ((float4*)Sb)[tid + 512] = sacc2;
        ((float4*)Sb)[tid + 768] = sacc3;
    }
    __syncthreads();

    float acc[4][4] = {};
    if (j > 0) {
        #pragma unroll 4
        for (int d = 0; d < 64; d++) {
            float4 a4 = *(const float4*)(QsT + d*64 + (ty<<2));
            float4 b4 = *(const float4*)(Sb  + d*64 + (tx<<2));
            float a[4] = {a4.x, a4.y, a4.z, a4.w};
            float b[4] = {b4.x, b4.y, b4.z, b4.w};
            #pragma unroll
            for (int i = 0; i < 4; i++)
                #pragma unroll
                for (int jj = 0; jj < 4; jj++)
                    acc[i][jj] += a[i] * b[jj];
        }
    }

    float pacc[4][4] = {};
    #pragma unroll 4
    for (int d = 0; d < 64; d++) {
        float4 a4 = *(const float4*)(QsT + d*64 + (ty<<2));
        float4 b4 = *(const float4*)(Xb  + d*64 + (tx<<2));
        float a[4] = {a4.x, a4.y, a4.z, a4.w};
        float b[4] = {b4.x, b4.y, b4.z, b4.w};
        #pragma unroll
        for (int i = 0; i < 4; i++)
            #pragma unroll
            for (int jj = 0; jj < 4; jj++)
                pacc[i][jj] += a[i] * b[jj];
    }
    #pragma unroll
    for (int i = 0; i < 4; i++)
        #pragma unroll
        for (int jj = 0; jj < 4; jj++)
            if ((tx<<2) + jj > (ty<<2) + i) pacc[i][jj] = 0.0f;
    __syncthreads();

    #pragma unroll
    for (int i = 0; i < 4; i++)
        *(float4*)(Sb + ((ty<<2)+i)*64 + (tx<<2)) =
            make_float4(pacc[i][0], pacc[i][1], pacc[i][2], pacc[i][3]);
    #pragma unroll
    for (int rep = 0; rep < 4; rep++) {
        const int g  = tid + rep * 256;
        const int r  = g >> 4;
        const int c4 = (g & 15) << 2;
        *(float4*)(Xb + r*64 + c4) = *(const float4*)(kch + r * HD + c4);
    }
    __syncthreads();

    #pragma unroll 4
    for (int s = 0; s < 64; s++) {
        float a[4];
        #pragma unroll
        for (int i = 0; i < 4; i++) a[i] = Sb[((ty<<2)+i)*64 + s];
        float4 b4 = *(const float4*)(Xb + s*64 + (tx<<2));
        float b[4] = {b4.x, b4.y, b4.z, b4.w};
        #pragma unroll
        for (int i = 0; i < 4; i++)
            #pragma unroll
            for (int jj = 0; jj < 4; jj++)
                acc[i][jj] += a[i] * b[jj];
    }
    __syncthreads();

    #pragma unroll
    for (int i = 0; i < 4; i++) {
        const float gi = 1.0f / (Greg[i] + EPSF);
        #pragma unroll
        for (int jj = 0; jj < 4; jj++) acc[i][jj] *= gi;
        *(float4*)(Sb + ((ty<<2)+i)*64 + (tx<<2)) =
            make_float4(acc[i][0], acc[i][1], acc[i][2], acc[i][3]);
    }
    __syncthreads();

    if (tid < 64) {
        float ss = 0.0f;
        #pragma unroll 8
        for (int d2 = 0; d2 < 64; d2++) {
            const float c = Sb[tid*64 + d2];
            ss += c * c;
        }
        Xb[tid] = fmaxf(sqrtf(ss), EPSF);
    }
    __syncthreads();

    #pragma unroll
    for (int i = 0; i < 4; i++) {
        const float ri = 1.0f / Xb[(ty<<2) + i];
        float4 o = make_float4(acc[i][0]*ri, acc[i][1]*ri, acc[i][2]*ri, acc[i][3]*ri);
        *(float4*)(g_unit + (l0 + (ty<<2) + i) * D + head * HD + (tx<<2)) = o;
    }
}

// ---------------- kernel 5: output projection (tf32 MMA, 64x64 tiles) ----
__global__ void __launch_bounds__(256)
oproj_kernel(const float* __restrict__ wo, const float* __restrict__ bo,
             float* __restrict__ out)
{
    __shared__ float Ah[64*TFS], Bh[64*TFS];
    const int m0 = blockIdx.y * 64;
    const int n0 = blockIdx.x * 64;

    float c[1][4][4] = {};
    tf32_gemm<1>(g_unit, wo, m0, n0, c, Ah, Bh);

    const int tid = threadIdx.x, lane = tid & 31, wid = tid >> 5;
    const int mw = wid >> 1, nw = wid & 1;
    const int row = lane >> 2, qc = (lane & 3) << 1;
    const int m = m0 + mw * 16 + row;
    #pragma unroll
    for (int ns = 0; ns < 4; ns++) {
        const int nc = n0 + nw * 32 + ns * 8 + qc;
        const float b0 = bo[nc], b1 = bo[nc + 1];
        *(float2*)(out + m * D + nc) =
            make_float2(c[0][ns][0] + b0, c[0][ns][1] + b1);
        *(float2*)(out + (m + 8) * D + nc) =
            make_float2(c[0][ns][2] + b0, c[0][ns][3] + b1);
    }
}

// ---------------- launch --------------------------------------------------
extern "C" void kernel_launch(void* const* d_in, const int* in_sizes, int n_in,
                              void* d_out, int out_size)
{
    const float* x   = (const float*)d_in[0];
    const float* phi = (const float*)d_in[1];
    const float* wq  = (const float*)d_in[2];
    const float* bq  = (const float*)d_in[3];
    const float* wk  = (const float*)d_in[4];
    const float* bk  = (const float*)d_in[5];
    const float* wv  = (const float*)d_in[6];
    const float* bv  = (const float*)d_in[7];
    const float* wo  = (const float*)d_in[8];
    const float* bo  = (const float*)d_in[9];
    const float* wg  = (const float*)d_in[10];
    const float* wgb = (const float*)d_in[11];
    float* out = (float*)d_out;

    qkv_kernel  <<<dim3(8, 8, 3), 256>>>(x, wq, bq, wk, bk, wv, bv);
    conv_kernel <<<dim3(40, 8, 2), 256>>>(phi);
    gate_kernel <<<dim3(16, 8), 256>>>(wg, wgb);
    ctxt_kernel <<<dim3(16, 8), 256>>>();
    oproj_kernel<<<dim3(8, 16), 256>>>(wo, bo, out);
}

// round 13
// speedup vs baseline: 1.3571x; 1.0096x over previous
#include <cuda_runtime.h>
#include <cstdint>

#define L   1024
#define D   512
#define H   8
#define HD  64
#define EPSF 1e-5f
#define SZ  (H*L*HD)          // 524288 elems per [H][L][HD] tensor

// ---------------- scratch (device globals; no allocation) ----------------
__device__ float g_q [SZ];
__device__ float g_k [SZ];
__device__ float g_v [SZ];
__device__ float g_kc[SZ];
__device__ float g_vc[SZ];
__device__ float g_gate[H*L];
__device__ float g_gcum[H*L];
__device__ float g_unit[L*D];
__device__ float g_cpart[2*4*SZ];   // conv partials: [z][chunk][H][L][HD]
__device__ float g_T[H*16*4096];    // per-tile state blocks T_j[m][n]
__device__ float g_S[H*16*4096];    // exclusive prefix of T: S_j = sum_{i<j} T_i

// Balanced triangular task map: 40 tasks per head, each <=4 s-tiles.
__device__ __forceinline__ void task_map(int t, int& lb, int& ch)
{
    int g, base;
    if      (t < 4)  { g = 0; base = 0;  }
    else if (t < 12) { g = 1; base = 4;  }
    else if (t < 24) { g = 2; base = 12; }
    else             { g = 3; base = 24; }
    const int idx = t - base;
    lb = g * 4 + idx / (g + 1);
    ch = idx % (g + 1);
}

// ================= single-pass tf32 MMA machinery ========================
__device__ __forceinline__ uint32_t f2tf32(float x)
{
    uint32_t r; asm("cvt.rna.tf32.f32 %0, %1;" : "=r"(r) : "f"(x)); return r;
}

__device__ __forceinline__ void mma_tf32(float c[4],
                                         const uint32_t a[4],
                                         const uint32_t b[2])
{
    asm("mma.sync.aligned.m16n8k8.row.col.f32.tf32.tf32.f32 "
        "{%0,%1,%2,%3}, {%4,%5,%6,%7}, {%8,%9}, {%0,%1,%2,%3};"
        : "+f"(c[0]), "+f"(c[1]), "+f"(c[2]), "+f"(c[3])
        : "r"(a[0]), "r"(a[1]), "r"(a[2]), "r"(a[3]),
          "r"(b[0]), "r"(b[1]));
}

// C[m][n] = sum_k A[m][k] * B[n][k]; block tile (64*MS)x64, K=512, 256 thr.
#define TFS 20
template<int MS>
__device__ __forceinline__ void tf32_gemm(
    const float* __restrict__ A, const float* __restrict__ B,
    int m0, int n0, float c[MS][4][4],
    float* Ah, float* Bh)
{
    const int tid  = threadIdx.x;
    const int lane = tid & 31;
    const int wid  = tid >> 5;
    const int mw   = wid >> 1;
    const int nw   = wid & 1;
    const int row  = lane >> 2;
    const int kq   = lane & 3;

    const uint32_t* uAh = (const uint32_t*)Ah;
    const uint32_t* uBh = (const uint32_t*)Bh;

    for (int k0 = 0; k0 < 512; k0 += 16) {
        __syncthreads();
        #pragma unroll
        for (int it = 0; it < MS; it++) {
            const int idx = tid + it * 256;
            const int r   = idx >> 2;
            const int c4  = (idx & 3) << 2;
            float4 g = *(const float4*)(A + (m0 + r) * 512 + k0 + c4);
            float4 hi4;
            hi4.x = __uint_as_float(f2tf32(g.x));
            hi4.y = __uint_as_float(f2tf32(g.y));
            hi4.z = __uint_as_float(f2tf32(g.z));
            hi4.w = __uint_as_float(f2tf32(g.w));
            *(float4*)(Ah + r * TFS + c4) = hi4;
        }
        {
            const int r  = tid >> 2;
            const int c4 = (tid & 3) << 2;
            float4 g = *(const float4*)(B + (n0 + r) * 512 + k0 + c4);
            float4 hi4;
            hi4.x = __uint_as_float(f2tf32(g.x));
            hi4.y = __uint_as_float(f2tf32(g.y));
            hi4.z = __uint_as_float(f2tf32(g.z));
            hi4.w = __uint_as_float(f2tf32(g.w));
            *(float4*)(Bh + r * TFS + c4) = hi4;
        }
        __syncthreads();

        #pragma unroll
        for (int k8 = 0; k8 < 16; k8 += 8) {
            uint32_t ah[MS][4], bh[4][2];
            #pragma unroll
            for (int ms = 0; ms < MS; ms++) {
                const int bi = (mw * (16 * MS) + ms * 16 + row) * TFS + k8 + kq;
                ah[ms][0] = uAh[bi];           ah[ms][1] = uAh[bi + 8*TFS];
                ah[ms][2] = uAh[bi + 4];       ah[ms][3] = uAh[bi + 8*TFS + 4];
            }
            #pragma unroll
            for (int ns = 0; ns < 4; ns++) {
                const int bi = (nw * 32 + ns * 8 + row) * TFS + k8 + kq;
                bh[ns][0] = uBh[bi];  bh[ns][1] = uBh[bi + 4];
            }
            #pragma unroll
            for (int ms = 0; ms < MS; ms++)
                #pragma unroll
                for (int ns = 0; ns < 4; ns++)
                    mma_tf32(c[ms][ns], ah[ms], bh[ns]);
        }
    }
}

// ---------------- kernel 1: fused QKV projections (tf32 MMA) -------------
__global__ void __launch_bounds__(256)
qkv_kernel(const float* __restrict__ x,
           const float* __restrict__ wq, const float* __restrict__ bq,
           const float* __restrict__ wk, const float* __restrict__ bk,
           const float* __restrict__ wv, const float* __restrict__ bv)
{
    __shared__ float Ah[128*TFS], Bh[64*TFS];
    const int z = blockIdx.z;
    const float* W    = (z == 0) ? wq : (z == 1) ? wk : wv;
    const float* bias = (z == 0) ? bq : (z == 1) ? bk : bv;
    float* out        = (z == 0) ? g_q : (z == 1) ? g_k : g_v;
    const float scale = (z == 1) ? 0.125f : 1.0f;

    const int head = blockIdx.x;
    const int m0 = blockIdx.y * 128;
    const int n0 = head * 64;

    float c[2][4][4] = {};
    tf32_gemm<2>(x, W, m0, n0, c, Ah, Bh);

    const int tid = threadIdx.x, lane = tid & 31, wid = tid >> 5;
    const int mw = wid >> 1, nw = wid & 1;
    const int row = lane >> 2, qc = (lane & 3) << 1;
    #pragma unroll
    for (int ms = 0; ms < 2; ms++) {
        const int m = m0 + mw * 32 + ms * 16 + row;
        #pragma unroll
        for (int ns = 0; ns < 4; ns++) {
            const int nc = nw * 32 + ns * 8 + qc;
            const float b0 = bias[n0 + nc], b1 = bias[n0 + nc + 1];
            float2 o0 = make_float2((c[ms][ns][0] + b0) * scale,
                                    (c[ms][ns][1] + b1) * scale);
            float2 o1 = make_float2((c[ms][ns][2] + b0) * scale,
                                    (c[ms][ns][3] + b1) * scale);
            *(float2*)(out + (head * L + m    ) * HD + nc) = o0;
            *(float2*)(out + (head * L + m + 8) * HD + nc) = o1;
        }
    }
}

// ---------------- kernel 2: causal Toeplitz conv, balanced chunks --------
// phi register-rotation: a_i(s+1) = a_{i-1}(s); 1 scalar LDS per s-step.
__global__ void __launch_bounds__(256)
conv_kernel(const float* __restrict__ phi)
{
    __shared__ float Ks[64*64];
    __shared__ float ph[130];          // +1 base shift so load index >= 0
    int lb, ch;
    task_map(blockIdx.x, lb, ch);
    const int head = blockIdx.y;
    const int z    = blockIdx.z;
    const float* src = (z ? g_v : g_k) + head * L * HD;
    float* dst = g_cpart + (z * 4 + ch) * SZ + head * L * HD;

    const int tid = threadIdx.x;
    const int tx = tid & 15, ty = tid >> 4;
    const int l0 = lb * 64;
    const int sb_beg = ch * 4;
    const int sb_end = min(sb_beg + 4, lb + 1);
    float acc[4][4] = {};

    for (int sb = sb_beg; sb < sb_end; sb++) {
        const int s0 = sb * 64;
        #pragma unroll
        for (int rep = 0; rep < 4; rep++) {
            const int g  = tid + rep * 256;
            const int r  = g >> 4;
            const int c4 = (g & 15) << 2;
            *(float4*)(Ks + r*64 + c4) = *(const float4*)(src + (s0 + r) * HD + c4);
        }
        if (tid < 127) {
            const int off = l0 - s0 - 63 + tid;
            ph[tid + 1] = (off >= 0) ? phi[off * H + head] : 0.0f;
        }
        if (tid == 127) ph[0] = 0.0f;
        __syncthreads();

        // a_i(s) = ph[64 + 4ty + i - s]; rotate each step, one new load.
        float a0 = ph[64 + (ty<<2)];
        float a1 = ph[65 + (ty<<2)];
        float a2 = ph[66 + (ty<<2)];
        float a3 = ph[67 + (ty<<2)];

        if (sb < lb) {
            #pragma unroll 4
            for (int s = 0; s < 64; s++) {
                float4 b4 = *(const float4*)(Ks + s*64 + (tx<<2));
                float b[4] = {b4.x, b4.y, b4.z, b4.w};
                float a[4] = {a0, a1, a2, a3};
                #pragma unroll
                for (int i = 0; i < 4; i++)
                    #pragma unroll
                    for (int j = 0; j < 4; j++) acc[i][j] += a[i] * b[j];
                a3 = a2; a2 = a1; a1 = a0;
                a0 = ph[63 + (ty<<2) - s];
            }
        } else {  // diagonal tile: causal mask l >= s
            #pragma unroll 4
            for (int s = 0; s < 64; s++) {
                float4 b4 = *(const float4*)(Ks + s*64 + (tx<<2));
                float b[4] = {b4.x, b4.y, b4.z, b4.w};
                float a[4] = {a0, a1, a2, a3};
                #pragma unroll
                for (int i = 0; i < 4; i++) {
                    const int ll = (ty<<2) + i;
                    const float av = (ll >= s) ? a[i] : 0.0f;
                    #pragma unroll
                    for (int j = 0; j < 4; j++) acc[i][j] += av * b[j];
                }
                a3 = a2; a2 = a1; a1 = a0;
                a0 = ph[63 + (ty<<2) - s];
            }
        }
        __syncthreads();
    }

    #pragma unroll
    for (int i = 0; i < 4; i++) {
        float4 o = make_float4(acc[i][0], acc[i][1], acc[i][2], acc[i][3]);
        *(float4*)(dst + (l0 + (ty<<2) + i) * HD + (tx<<2)) = o;
    }
}

// ---------------- kernel 3: conv-finalize + gates + state block T_j ------
__global__ void __launch_bounds__(256)
gate_kernel(const float* __restrict__ wg, const float* __restrict__ wgb)
{
    __shared__ float sm[12288];
    float* KsT   = sm;                  // [n][l] finalized Kc transposed
    float* wgT   = sm + 4096;           // [n][m]; phase B: Ksn [s][n]
    float* Vcs   = sm + 8192;           // [s][m] finalized Vc
    float* red   = sm;                  // alias after phase A reads
    float* gvals = sm + 1536;

    const int lb = blockIdx.x, head = blockIdx.y;
    const int l0 = lb * 64;
    const int nchunks = (lb >> 2) + 1;
    const float* kp = g_cpart + head * L * HD + l0 * HD;            // z=0,ch=0
    const float* vp = g_cpart + 4 * SZ + head * L * HD + l0 * HD;   // z=1,ch=0

    const int tid = threadIdx.x;
    const int tx = tid & 15, ty = tid >> 4;

    #pragma unroll
    for (int rep = 0; rep < 4; rep++) {
        const int g  = tid + rep * 256;
        const int r  = g >> 4;
        const int c4 = (g & 15) << 2;
        const int off = r * HD + c4;

        float4 kv = *(const float4*)(kp + off);
        for (int c = 1; c < nchunks; c++) {
            float4 p = *(const float4*)(kp + c * SZ + off);
            kv.x += p.x; kv.y += p.y; kv.z += p.z; kv.w += p.w;
        }
        *(float4*)(g_kc + (head * L + l0 + r) * HD + c4) = kv;
        KsT[(c4+0)*64 + r] = kv.x;
        KsT[(c4+1)*64 + r] = kv.y;
        KsT[(c4+2)*64 + r] = kv.z;
        KsT[(c4+3)*64 + r] = kv.w;

        float4 vv = *(const float4*)(vp + off);
        for (int c = 1; c < nchunks; c++) {
            float4 p = *(const float4*)(vp + c * SZ + off);
            vv.x += p.x; vv.y += p.y; vv.z += p.z; vv.w += p.w;
        }
        *(float4*)(g_vc + (head * L + l0 + r) * HD + c4) = vv;
        *(float4*)(Vcs + r*64 + c4) = vv;

        float4 wv = *(const float4*)(wg + r * 64 + c4);
        wgT[(c4+0)*64 + r] = wv.x;
        wgT[(c4+1)*64 + r] = wv.y;
        wgT[(c4+2)*64 + r] = wv.z;
        wgT[(c4+3)*64 + r] = wv.w;
    }
    __syncthreads();

    // Phase A: Tg[l][m] = sum_n kc[l,n]*W[m,n]; psum = <Tg[l], vc[l]>
    float acc[4][4] = {};
    #pragma unroll 4
    for (int n = 0; n < 64; n++) {
        float4 a4 = *(const float4*)(KsT + n*64 + (ty<<2));
        float4 b4 = *(const float4*)(wgT + n*64 + (tx<<2));
        float a[4] = {a4.x, a4.y, a4.z, a4.w};
        float b[4] = {b4.x, b4.y, b4.z, b4.w};
        #pragma unroll
        for (int i = 0; i < 4; i++)
            #pragma unroll
            for (int j = 0; j < 4; j++)
                acc[i][j] += a[i] * b[j];
    }
    float psum[4];
    #pragma unroll
    for (int i = 0; i < 4; i++) {
        float4 v4 = *(const float4*)(Vcs + ((ty<<2)+i)*64 + (tx<<2));
        psum[i] = acc[i][0]*v4.x + acc[i][1]*v4.y + acc[i][2]*v4.z + acc[i][3]*v4.w;
    }
    __syncthreads();
    #pragma unroll
    for (int i = 0; i < 4; i++)
        red[((ty<<2)+i)*16 + tx] = psum[i];
    __syncthreads();

    if (tid < 64) {
        float s = 0.0f;
        #pragma unroll
        for (int t = 0; t < 16; t++) s += red[tid*16 + t];
        const float r = fmaxf(s + wgb[0], 0.0f);
        const float gv = r * r + EPSF;
        g_gate[head * L + l0 + tid] = gv;
        gvals[tid] = gv;
    }
    __syncthreads();

    // Phase B: reload own finalized Kc (L1-hot) natural into wgT area
    float* Ksn = wgT;
    const float* kch = g_kc + (head * L + l0) * HD;
    #pragma unroll
    for (int rep = 0; rep < 4; rep++) {
        const int g  = tid + rep * 256;
        const int r  = g >> 4;
        const int c4 = (g & 15) << 2;
        *(float4*)(Ksn + r*64 + c4) = *(const float4*)(kch + r * HD + c4);
    }
    #pragma unroll
    for (int k = 0; k < 4; k++) {
        const int f = tid + k * 256;
        const float gv = gvals[f >> 4];
        float4 v = ((float4*)Vcs)[f];
        v.x *= gv; v.y *= gv; v.z *= gv; v.w *= gv;
        ((float4*)Vcs)[f] = v;
    }
    __syncthreads();

    float tacc[4][4] = {};
    #pragma unroll 4
    for (int s = 0; s < 64; s++) {
        float4 a4 = *(const float4*)(Vcs + s*64 + (ty<<2));
        float4 b4 = *(const float4*)(Ksn + s*64 + (tx<<2));
        float a[4] = {a4.x, a4.y, a4.z, a4.w};
        float b[4] = {b4.x, b4.y, b4.z, b4.w};
        #pragma unroll
        for (int i = 0; i < 4; i++)
            #pragma unroll
            for (int j = 0; j < 4; j++)
                tacc[i][j] += a[i] * b[j];
    }
    float* dst = g_T + (head * 16 + lb) * 4096;
    #pragma unroll
    for (int i = 0; i < 4; i++)
        *(float4*)(dst + ((ty<<2)+i)*64 + (tx<<2)) =
            make_float4(tacc[i][0], tacc[i][1], tacc[i][2], tacc[i][3]);
}

// ---------------- kernel 4: prescan (T prefix + gate scan) ---------------
// grid (8, 5): y<4 -> exclusive running sum of T tiles (ascending i, same
// order as the old in-ctxt loop -> bitwise identical); y==4 -> gate scan.
__global__ void __launch_bounds__(256)
prescan_kernel()
{
    const int head = blockIdx.x;
    const int part = blockIdx.y;
    if (part < 4) {
        const int f = part * 256 + threadIdx.x;      // float4 idx in [0,1024)
        const float4* tbase = (const float4*)(g_T + head * 16 * 4096);
        float4* sbase = (float4*)(g_S + head * 16 * 4096);
        float4 run = make_float4(0.f, 0.f, 0.f, 0.f);
        #pragma unroll
        for (int i = 0; i < 16; i++) {
            sbase[i * 1024 + f] = run;
            float4 p = tbase[i * 1024 + f];
            run.x += p.x; run.y += p.y; run.z += p.z; run.w += p.w;
        }
    } else {
        __shared__ float sb[256];
        const int tid = threadIdx.x;
        const float* gfull = g_gate + head * L;
        float4 gv = *(const float4*)(gfull + tid * 4);
        const float p0 = gv.x;
        const float p1 = p0 + gv.y;
        const float p2 = p1 + gv.z;
        const float p3 = p2 + gv.w;
        sb[tid] = p3;
        __syncthreads();
        for (int off = 1; off < 256; off <<= 1) {
            const float v = (tid >= off) ? sb[tid - off] : 0.0f;
            __syncthreads();
            sb[tid] += v;
            __syncthreads();
        }
        const float excl = sb[tid] - p3;
        float4 o = make_float4(excl + p0, excl + p1, excl + p2, excl + p3);
        *(float4*)(g_gcum + head * L + tid * 4) = o;
    }
}

// ---------------- kernel 5: chunked-state attention + normalize ----------
// Uniform work: S_{j-1} precomputed in g_S; gcum precomputed in g_gcum.
__global__ void __launch_bounds__(256)
ctxt_kernel()
{
    __shared__ float sm[12288];
    float* QsT = sm;
    float* Sb  = sm + 4096;
    float* Xb  = sm + 8192;

    const int j = blockIdx.x, head = blockIdx.y;
    const int l0 = j * 64;
    const float* qh  = g_q  + (head * L + l0) * HD;
    const float* kch = g_kc + (head * L + l0) * HD;
    const float* vch = g_vc + (head * L + l0) * HD;
    const float* gh  = g_gate + head * L + l0;

    const int tid = threadIdx.x;
    const int tx = tid & 15, ty = tid >> 4;

    float Greg[4];
    #pragma unroll
    for (int i = 0; i < 4; i++)
        Greg[i] = g_gcum[head * L + l0 + (ty<<2) + i];

    #pragma unroll
    for (int rep = 0; rep < 4; rep++) {
        const int g  = tid + rep * 256;
        const int r  = g >> 4;
        const int c4 = (g & 15) << 2;
        float4 q4 = *(const float4*)(qh + r * HD + c4);
        QsT[(c4+0)*64 + r] = q4.x;
        QsT[(c4+1)*64 + r] = q4.y;
        QsT[(c4+2)*64 + r] = q4.z;
        QsT[(c4+3)*64 + r] = q4.w;
        const float gs = gh[r];
        float4 v4 = *(const float4*)(vch + r * HD + c4);
        Xb[(c4+0)*64 + r] = v4.x * gs;
        Xb[(c4+1)*64 + r] = v4.y * gs;
        Xb[(c4+2)*64 + r] = v4.z * gs;
        Xb[(c4+3)*64 + r] = v4.w * gs;
    }
    {
        const float4* sp = (const float4*)(g_S + (head * 16 + j) * 4096);
        ((float4*)Sb)[tid +   0] = sp[tid +   0];
        ((float4*)Sb)[tid + 256] = sp[tid + 256];
        ((float4*)Sb)[tid + 512] = sp[tid + 512];
        ((float4*)Sb)[tid + 768] = sp[tid + 768];
    }
    __syncthreads();

    float acc[4][4] = {};
    if (j > 0) {
        #pragma unroll 4
        for (int d = 0; d < 64; d++) {
            float4 a4 = *(const float4*)(QsT + d*64 + (ty<<2));
            float4 b4 = *(const float4*)(Sb  + d*64 + (tx<<2));
            float a[4] = {a4.x, a4.y, a4.z, a4.w};
            float b[4] = {b4.x, b4.y, b4.z, b4.w};
            #pragma unroll
            for (int i = 0; i < 4; i++)
                #pragma unroll
                for (int jj = 0; jj < 4; jj++)
                    acc[i][jj] += a[i] * b[jj];
        }
    }

    float pacc[4][4] = {};
    #pragma unroll 4
    for (int d = 0; d < 64; d++) {
        float4 a4 = *(const float4*)(QsT + d*64 + (ty<<2));
        float4 b4 = *(const float4*)(Xb  + d*64 + (tx<<2));
        float a[4] = {a4.x, a4.y, a4.z, a4.w};
        float b[4] = {b4.x, b4.y, b4.z, b4.w};
        #pragma unroll
        for (int i = 0; i < 4; i++)
            #pragma unroll
            for (int jj = 0; jj < 4; jj++)
                pacc[i][jj] += a[i] * b[jj];
    }
    #pragma unroll
    for (int i = 0; i < 4; i++)
        #pragma unroll
        for (int jj = 0; jj < 4; jj++)
            if ((tx<<2) + jj > (ty<<2) + i) pacc[i][jj] = 0.0f;
    __syncthreads();

    #pragma unroll
    for (int i = 0; i < 4; i++)
        *(float4*)(Sb + ((ty<<2)+i)*64 + (tx<<2)) =
            make_float4(pacc[i][0], pacc[i][1], pacc[i][2], pacc[i][3]);
    #pragma unroll
    for (int rep = 0; rep < 4; rep++) {
        const int g  = tid + rep * 256;
        const int r  = g >> 4;
        const int c4 = (g & 15) << 2;
        *(float4*)(Xb + r*64 + c4) = *(const float4*)(kch + r * HD + c4);
    }
    __syncthreads();

    #pragma unroll 4
    for (int s = 0; s < 64; s++) {
        float a[4];
        #pragma unroll
        for (int i = 0; i < 4; i++) a[i] = Sb[((ty<<2)+i)*64 + s];
        float4 b4 = *(const float4*)(Xb + s*64 + (tx<<2));
        float b[4] = {b4.x, b4.y, b4.z, b4.w};
        #pragma unroll
        for (int i = 0; i < 4; i++)
            #pragma unroll
            for (int jj = 0; jj < 4; jj++)
                acc[i][jj] += a[i] * b[jj];
    }
    __syncthreads();

    #pragma unroll
    for (int i = 0; i < 4; i++) {
        const float gi = 1.0f / (Greg[i] + EPSF);
        #pragma unroll
        for (int jj = 0; jj < 4; jj++) acc[i][jj] *= gi;
        *(float4*)(Sb + ((ty<<2)+i)*64 + (tx<<2)) =
            make_float4(acc[i][0], acc[i][1], acc[i][2], acc[i][3]);
    }
    __syncthreads();

    if (tid < 64) {
        float ss = 0.0f;
        #pragma unroll 8
        for (int d2 = 0; d2 < 64; d2++) {
            const float c = Sb[tid*64 + d2];
            ss += c * c;
        }
        Xb[tid] = fmaxf(sqrtf(ss), EPSF);
    }
    __syncthreads();

    #pragma unroll
    for (int i = 0; i < 4; i++) {
        const float ri = 1.0f / Xb[(ty<<2) + i];
        float4 o = make_float4(acc[i][0]*ri, acc[i][1]*ri, acc[i][2]*ri, acc[i][3]*ri);
        *(float4*)(g_unit + (l0 + (ty<<2) + i) * D + head * HD + (tx<<2)) = o;
    }
}

// ---------------- kernel 6: output projection (tf32 MMA, 64x64 tiles) ----
__global__ void __launch_bounds__(256)
oproj_kernel(const float* __restrict__ wo, const float* __restrict__ bo,
             float* __restrict__ out)
{
    __shared__ float Ah[64*TFS], Bh[64*TFS];
    const int m0 = blockIdx.y * 64;
    const int n0 = blockIdx.x * 64;

    float c[1][4][4] = {};
    tf32_gemm<1>(g_unit, wo, m0, n0, c, Ah, Bh);

    const int tid = threadIdx.x, lane = tid & 31, wid = tid >> 5;
    const int mw = wid >> 1, nw = wid & 1;
    const int row = lane >> 2, qc = (lane & 3) << 1;
    const int m = m0 + mw * 16 + row;
    #pragma unroll
    for (int ns = 0; ns < 4; ns++) {
        const int nc = n0 + nw * 32 + ns * 8 + qc;
        const float b0 = bo[nc], b1 = bo[nc + 1];
        *(float2*)(out + m * D + nc) =
            make_float2(c[0][ns][0] + b0, c[0][ns][1] + b1);
        *(float2*)(out + (m + 8) * D + nc) =
            make_float2(c[0][ns][2] + b0, c[0][ns][3] + b1);
    }
}

// ---------------- launch --------------------------------------------------
extern "C" void kernel_launch(void* const* d_in, const int* in_sizes, int n_in,
                              void* d_out, int out_size)
{
    const float* x   = (const float*)d_in[0];
    const float* phi = (const float*)d_in[1];
    const float* wq  = (const float*)d_in[2];
    const float* bq  = (const float*)d_in[3];
    const float* wk  = (const float*)d_in[4];
    const float* bk  = (const float*)d_in[5];
    const float* wv  = (const float*)d_in[6];
    const float* bv  = (const float*)d_in[7];
    const float* wo  = (const float*)d_in[8];
    const float* bo  = (const float*)d_in[9];
    const float* wg  = (const float*)d_in[10];
    const float* wgb = (const float*)d_in[11];
    float* out = (float*)d_out;

    qkv_kernel    <<<dim3(8, 8, 3), 256>>>(x, wq, bq, wk, bk, wv, bv);
    conv_kernel   <<<dim3(40, 8, 2), 256>>>(phi);
    gate_kernel   <<<dim3(16, 8), 256>>>(wg, wgb);
    prescan_kernel<<<dim3(8, 5), 256>>>();
    ctxt_kernel   <<<dim3(16, 8), 256>>>();
    oproj_kernel  <<<dim3(8, 16), 256>>>(wo, bo, out);
}

// round 14
// speedup vs baseline: 1.3807x; 1.0174x over previous
#include <cuda_runtime.h>
#include <cstdint>

#define L   1024
#define D   512
#define H   8
#define HD  64
#define EPSF 1e-5f
#define SZ  (H*L*HD)          // 524288 elems per [H][L][HD] tensor

// ---------------- scratch (device globals; no allocation) ----------------
__device__ float g_q [SZ];
__device__ float g_k [SZ];
__device__ float g_v [SZ];
__device__ float g_kc[SZ];
__device__ float g_vc[SZ];
__device__ float g_gate[H*L];
__device__ float g_gcum[H*L];
__device__ float g_unit[L*D];
__device__ float g_cpart[2*4*SZ];   // conv partials: [z][chunk][H][L][HD]
__device__ float g_T[H*16*4096];    // per-tile state blocks T_j[m][n]
__device__ float g_S[H*16*4096];    // exclusive prefix of T: S_j = sum_{i<j} T_i

// Balanced triangular task map: 40 tasks per head, each <=4 s-tiles.
__device__ __forceinline__ void task_map(int t, int& lb, int& ch)
{
    int g, base;
    if      (t < 4)  { g = 0; base = 0;  }
    else if (t < 12) { g = 1; base = 4;  }
    else if (t < 24) { g = 2; base = 12; }
    else             { g = 3; base = 24; }
    const int idx = t - base;
    lb = g * 4 + idx / (g + 1);
    ch = idx % (g + 1);
}

// ================= single-pass tf32 MMA machinery ========================
__device__ __forceinline__ uint32_t f2tf32(float x)
{
    uint32_t r; asm("cvt.rna.tf32.f32 %0, %1;" : "=r"(r) : "f"(x)); return r;
}

__device__ __forceinline__ void mma_tf32(float c[4],
                                         const uint32_t a[4],
                                         const uint32_t b[2])
{
    asm("mma.sync.aligned.m16n8k8.row.col.f32.tf32.tf32.f32 "
        "{%0,%1,%2,%3}, {%4,%5,%6,%7}, {%8,%9}, {%0,%1,%2,%3};"
        : "+f"(c[0]), "+f"(c[1]), "+f"(c[2]), "+f"(c[3])
        : "r"(a[0]), "r"(a[1]), "r"(a[2]), "r"(a[3]),
          "r"(b[0]), "r"(b[1]));
}

// C[m][n] = sum_k A[m][k] * B[n][k]; block tile (64*MS)x64, K=512, 256 thr.
#define TFS 20
template<int MS>
__device__ __forceinline__ void tf32_gemm(
    const float* __restrict__ A, const float* __restrict__ B,
    int m0, int n0, float c[MS][4][4],
    float* Ah, float* Bh)
{
    const int tid  = threadIdx.x;
    const int lane = tid & 31;
    const int wid  = tid >> 5;
    const int mw   = wid >> 1;
    const int nw   = wid & 1;
    const int row  = lane >> 2;
    const int kq   = lane & 3;

    const uint32_t* uAh = (const uint32_t*)Ah;
    const uint32_t* uBh = (const uint32_t*)Bh;

    for (int k0 = 0; k0 < 512; k0 += 16) {
        __syncthreads();
        #pragma unroll
        for (int it = 0; it < MS; it++) {
            const int idx = tid + it * 256;
            const int r   = idx >> 2;
            const int c4  = (idx & 3) << 2;
            float4 g = *(const float4*)(A + (m0 + r) * 512 + k0 + c4);
            float4 hi4;
            hi4.x = __uint_as_float(f2tf32(g.x));
            hi4.y = __uint_as_float(f2tf32(g.y));
            hi4.z = __uint_as_float(f2tf32(g.z));
            hi4.w = __uint_as_float(f2tf32(g.w));
            *(float4*)(Ah + r * TFS + c4) = hi4;
        }
        {
            const int r  = tid >> 2;
            const int c4 = (tid & 3) << 2;
            float4 g = *(const float4*)(B + (n0 + r) * 512 + k0 + c4);
            float4 hi4;
            hi4.x = __uint_as_float(f2tf32(g.x));
            hi4.y = __uint_as_float(f2tf32(g.y));
            hi4.z = __uint_as_float(f2tf32(g.z));
            hi4.w = __uint_as_float(f2tf32(g.w));
            *(float4*)(Bh + r * TFS + c4) = hi4;
        }
        __syncthreads();

        #pragma unroll
        for (int k8 = 0; k8 < 16; k8 += 8) {
            uint32_t ah[MS][4], bh[4][2];
            #pragma unroll
            for (int ms = 0; ms < MS; ms++) {
                const int bi = (mw * (16 * MS) + ms * 16 + row) * TFS + k8 + kq;
                ah[ms][0] = uAh[bi];           ah[ms][1] = uAh[bi + 8*TFS];
                ah[ms][2] = uAh[bi + 4];       ah[ms][3] = uAh[bi + 8*TFS + 4];
            }
            #pragma unroll
            for (int ns = 0; ns < 4; ns++) {
                const int bi = (nw * 32 + ns * 8 + row) * TFS + k8 + kq;
                bh[ns][0] = uBh[bi];  bh[ns][1] = uBh[bi + 4];
            }
            #pragma unroll
            for (int ms = 0; ms < MS; ms++)
                #pragma unroll
                for (int ns = 0; ns < 4; ns++)
                    mma_tf32(c[ms][ns], ah[ms], bh[ns]);
        }
    }
}

// ---------------- kernel 1: fused QKV projections (tf32 MMA) -------------
__global__ void __launch_bounds__(256)
qkv_kernel(const float* __restrict__ x,
           const float* __restrict__ wq, const float* __restrict__ bq,
           const float* __restrict__ wk, const float* __restrict__ bk,
           const float* __restrict__ wv, const float* __restrict__ bv)
{
    __shared__ float Ah[128*TFS], Bh[64*TFS];
    const int z = blockIdx.z;
    const float* W    = (z == 0) ? wq : (z == 1) ? wk : wv;
    const float* bias = (z == 0) ? bq : (z == 1) ? bk : bv;
    float* out        = (z == 0) ? g_q : (z == 1) ? g_k : g_v;
    const float scale = (z == 1) ? 0.125f : 1.0f;

    const int head = blockIdx.x;
    const int m0 = blockIdx.y * 128;
    const int n0 = head * 64;

    float c[2][4][4] = {};
    tf32_gemm<2>(x, W, m0, n0, c, Ah, Bh);

    const int tid = threadIdx.x, lane = tid & 31, wid = tid >> 5;
    const int mw = wid >> 1, nw = wid & 1;
    const int row = lane >> 2, qc = (lane & 3) << 1;
    #pragma unroll
    for (int ms = 0; ms < 2; ms++) {
        const int m = m0 + mw * 32 + ms * 16 + row;
        #pragma unroll
        for (int ns = 0; ns < 4; ns++) {
            const int nc = nw * 32 + ns * 8 + qc;
            const float b0 = bias[n0 + nc], b1 = bias[n0 + nc + 1];
            float2 o0 = make_float2((c[ms][ns][0] + b0) * scale,
                                    (c[ms][ns][1] + b1) * scale);
            float2 o1 = make_float2((c[ms][ns][2] + b0) * scale,
                                    (c[ms][ns][3] + b1) * scale);
            *(float2*)(out + (head * L + m    ) * HD + nc) = o0;
            *(float2*)(out + (head * L + m + 8) * HD + nc) = o1;
        }
    }
}

// ---------------- kernel 2: causal Toeplitz conv, balanced chunks --------
// phi register-rotation: a_i(s+1) = a_{i-1}(s); 1 scalar LDS per s-step.
__global__ void __launch_bounds__(256)
conv_kernel(const float* __restrict__ phi)
{
    __shared__ float Ks[64*64];
    __shared__ float ph[130];          // +1 base shift so load index >= 0
    int lb, ch;
    task_map(blockIdx.x, lb, ch);
    const int head = blockIdx.y;
    const int z    = blockIdx.z;
    const float* src = (z ? g_v : g_k) + head * L * HD;
    float* dst = g_cpart + (z * 4 + ch) * SZ + head * L * HD;

    const int tid = threadIdx.x;
    const int tx = tid & 15, ty = tid >> 4;
    const int l0 = lb * 64;
    const int sb_beg = ch * 4;
    const int sb_end = min(sb_beg + 4, lb + 1);
    float acc[4][4] = {};

    for (int sb = sb_beg; sb < sb_end; sb++) {
        const int s0 = sb * 64;
        #pragma unroll
        for (int rep = 0; rep < 4; rep++) {
            const int g  = tid + rep * 256;
            const int r  = g >> 4;
            const int c4 = (g & 15) << 2;
            *(float4*)(Ks + r*64 + c4) = *(const float4*)(src + (s0 + r) * HD + c4);
        }
        if (tid < 127) {
            const int off = l0 - s0 - 63 + tid;
            ph[tid + 1] = (off >= 0) ? phi[off * H + head] : 0.0f;
        }
        if (tid == 127) ph[0] = 0.0f;
        __syncthreads();

        float a0 = ph[64 + (ty<<2)];
        float a1 = ph[65 + (ty<<2)];
        float a2 = ph[66 + (ty<<2)];
        float a3 = ph[67 + (ty<<2)];

        if (sb < lb) {
            #pragma unroll 4
            for (int s = 0; s < 64; s++) {
                float4 b4 = *(const float4*)(Ks + s*64 + (tx<<2));
                float b[4] = {b4.x, b4.y, b4.z, b4.w};
                float a[4] = {a0, a1, a2, a3};
                #pragma unroll
                for (int i = 0; i < 4; i++)
                    #pragma unroll
                    for (int j = 0; j < 4; j++) acc[i][j] += a[i] * b[j];
                a3 = a2; a2 = a1; a1 = a0;
                a0 = ph[63 + (ty<<2) - s];
            }
        } else {  // diagonal tile: causal mask l >= s
            #pragma unroll 4
            for (int s = 0; s < 64; s++) {
                float4 b4 = *(const float4*)(Ks + s*64 + (tx<<2));
                float b[4] = {b4.x, b4.y, b4.z, b4.w};
                float a[4] = {a0, a1, a2, a3};
                #pragma unroll
                for (int i = 0; i < 4; i++) {
                    const int ll = (ty<<2) + i;
                    const float av = (ll >= s) ? a[i] : 0.0f;
                    #pragma unroll
                    for (int j = 0; j < 4; j++) acc[i][j] += av * b[j];
                }
                a3 = a2; a2 = a1; a1 = a0;
                a0 = ph[63 + (ty<<2) - s];
            }
        }
        __syncthreads();
    }

    #pragma unroll
    for (int i = 0; i < 4; i++) {
        float4 o = make_float4(acc[i][0], acc[i][1], acc[i][2], acc[i][3]);
        *(float4*)(dst + (l0 + (ty<<2) + i) * HD + (tx<<2)) = o;
    }
}

// ---------------- kernel 3: conv-finalize + gates + state block T_j ------
__global__ void __launch_bounds__(256)
gate_kernel(const float* __restrict__ wg, const float* __restrict__ wgb)
{
    __shared__ float sm[12288];
    float* KsT   = sm;                  // [n][l] finalized Kc transposed
    float* wgT   = sm + 4096;           // [n][m]; phase B: Ksn [s][n]
    float* Vcs   = sm + 8192;           // [s][m] finalized Vc
    float* red   = sm;                  // alias after phase A reads
    float* gvals = sm + 1536;

    const int lb = blockIdx.x, head = blockIdx.y;
    const int l0 = lb * 64;
    const int nchunks = (lb >> 2) + 1;
    const float* kp = g_cpart + head * L * HD + l0 * HD;            // z=0,ch=0
    const float* vp = g_cpart + 4 * SZ + head * L * HD + l0 * HD;   // z=1,ch=0

    const int tid = threadIdx.x;
    const int tx = tid & 15, ty = tid >> 4;

    #pragma unroll
    for (int rep = 0; rep < 4; rep++) {
        const int g  = tid + rep * 256;
        const int r  = g >> 4;
        const int c4 = (g & 15) << 2;
        const int off = r * HD + c4;

        float4 kv = *(const float4*)(kp + off);
        for (int c = 1; c < nchunks; c++) {
            float4 p = *(const float4*)(kp + c * SZ + off);
            kv.x += p.x; kv.y += p.y; kv.z += p.z; kv.w += p.w;
        }
        *(float4*)(g_kc + (head * L + l0 + r) * HD + c4) = kv;
        KsT[(c4+0)*64 + r] = kv.x;
        KsT[(c4+1)*64 + r] = kv.y;
        KsT[(c4+2)*64 + r] = kv.z;
        KsT[(c4+3)*64 + r] = kv.w;

        float4 vv = *(const float4*)(vp + off);
        for (int c = 1; c < nchunks; c++) {
            float4 p = *(const float4*)(vp + c * SZ + off);
            vv.x += p.x; vv.y += p.y; vv.z += p.z; vv.w += p.w;
        }
        *(float4*)(g_vc + (head * L + l0 + r) * HD + c4) = vv;
        *(float4*)(Vcs + r*64 + c4) = vv;

        float4 wv = *(const float4*)(wg + r * 64 + c4);
        wgT[(c4+0)*64 + r] = wv.x;
        wgT[(c4+1)*64 + r] = wv.y;
        wgT[(c4+2)*64 + r] = wv.z;
        wgT[(c4+3)*64 + r] = wv.w;
    }
    __syncthreads();

    // Phase A: Tg[l][m] = sum_n kc[l,n]*W[m,n]; psum = <Tg[l], vc[l]>
    float acc[4][4] = {};
    #pragma unroll 4
    for (int n = 0; n < 64; n++) {
        float4 a4 = *(const float4*)(KsT + n*64 + (ty<<2));
        float4 b4 = *(const float4*)(wgT + n*64 + (tx<<2));
        float a[4] = {a4.x, a4.y, a4.z, a4.w};
        float b[4] = {b4.x, b4.y, b4.z, b4.w};
        #pragma unroll
        for (int i = 0; i < 4; i++)
            #pragma unroll
            for (int j = 0; j < 4; j++)
                acc[i][j] += a[i] * b[j];
    }
    float psum[4];
    #pragma unroll
    for (int i = 0; i < 4; i++) {
        float4 v4 = *(const float4*)(Vcs + ((ty<<2)+i)*64 + (tx<<2));
        psum[i] = acc[i][0]*v4.x + acc[i][1]*v4.y + acc[i][2]*v4.z + acc[i][3]*v4.w;
    }
    __syncthreads();
    #pragma unroll
    for (int i = 0; i < 4; i++)
        red[((ty<<2)+i)*16 + tx] = psum[i];
    __syncthreads();

    if (tid < 64) {
        float s = 0.0f;
        #pragma unroll
        for (int t = 0; t < 16; t++) s += red[tid*16 + t];
        const float r = fmaxf(s + wgb[0], 0.0f);
        const float gv = r * r + EPSF;
        g_gate[head * L + l0 + tid] = gv;
        gvals[tid] = gv;
    }
    __syncthreads();

    // Phase B: reload own finalized Kc (L1-hot) natural into wgT area
    float* Ksn = wgT;
    const float* kch = g_kc + (head * L + l0) * HD;
    #pragma unroll
    for (int rep = 0; rep < 4; rep++) {
        const int g  = tid + rep * 256;
        const int r  = g >> 4;
        const int c4 = (g & 15) << 2;
        *(float4*)(Ksn + r*64 + c4) = *(const float4*)(kch + r * HD + c4);
    }
    #pragma unroll
    for (int k = 0; k < 4; k++) {
        const int f = tid + k * 256;
        const float gv = gvals[f >> 4];
        float4 v = ((float4*)Vcs)[f];
        v.x *= gv; v.y *= gv; v.z *= gv; v.w *= gv;
        ((float4*)Vcs)[f] = v;
    }
    __syncthreads();

    float tacc[4][4] = {};
    #pragma unroll 4
    for (int s = 0; s < 64; s++) {
        float4 a4 = *(const float4*)(Vcs + s*64 + (ty<<2));
        float4 b4 = *(const float4*)(Ksn + s*64 + (tx<<2));
        float a[4] = {a4.x, a4.y, a4.z, a4.w};
        float b[4] = {b4.x, b4.y, b4.z, b4.w};
        #pragma unroll
        for (int i = 0; i < 4; i++)
            #pragma unroll
            for (int j = 0; j < 4; j++)
                tacc[i][j] += a[i] * b[j];
    }
    float* dst = g_T + (head * 16 + lb) * 4096;
    #pragma unroll
    for (int i = 0; i < 4; i++)
        *(float4*)(dst + ((ty<<2)+i)*64 + (tx<<2)) =
            make_float4(tacc[i][0], tacc[i][1], tacc[i][2], tacc[i][3]);
}

// ---------------- kernel 4: prescan (T prefix + gate scan) ---------------
// grid (8, 5): y<4 -> exclusive running sum of T tiles with 4-deep load
// batching (MLP=4; accumulation order ascending i -> bitwise identical);
// y==4 -> gate scan.
__global__ void __launch_bounds__(256)
prescan_kernel()
{
    const int head = blockIdx.x;
    const int part = blockIdx.y;
    if (part < 4) {
        const int f = part * 256 + threadIdx.x;      // float4 idx in [0,1024)
        const float4* tbase = (const float4*)(g_T + head * 16 * 4096);
        float4* sbase = (float4*)(g_S + head * 16 * 4096);
        float4 run = make_float4(0.f, 0.f, 0.f, 0.f);
        #pragma unroll
        for (int i = 0; i < 16; i += 4) {
            // 4 independent loads in flight before any accumulate
            float4 p0 = tbase[(i+0) * 1024 + f];
            float4 p1 = tbase[(i+1) * 1024 + f];
            float4 p2 = tbase[(i+2) * 1024 + f];
            float4 p3 = tbase[(i+3) * 1024 + f];
            sbase[(i+0) * 1024 + f] = run;
            run.x += p0.x; run.y += p0.y; run.z += p0.z; run.w += p0.w;
            sbase[(i+1) * 1024 + f] = run;
            run.x += p1.x; run.y += p1.y; run.z += p1.z; run.w += p1.w;
            sbase[(i+2) * 1024 + f] = run;
            run.x += p2.x; run.y += p2.y; run.z += p2.z; run.w += p2.w;
            sbase[(i+3) * 1024 + f] = run;
            run.x += p3.x; run.y += p3.y; run.z += p3.z; run.w += p3.w;
        }
    } else {
        __shared__ float sb[256];
        const int tid = threadIdx.x;
        const float* gfull = g_gate + head * L;
        float4 gv = *(const float4*)(gfull + tid * 4);
        const float p0 = gv.x;
        const float p1 = p0 + gv.y;
        const float p2 = p1 + gv.z;
        const float p3 = p2 + gv.w;
        sb[tid] = p3;
        __syncthreads();
        for (int off = 1; off < 256; off <<= 1) {
            const float v = (tid >= off) ? sb[tid - off] : 0.0f;
            __syncthreads();
            sb[tid] += v;
            __syncthreads();
        }
        const float excl = sb[tid] - p3;
        float4 o = make_float4(excl + p0, excl + p1, excl + p2, excl + p3);
        *(float4*)(g_gcum + head * L + tid * 4) = o;
    }
}

// ---------------- kernel 5: chunked-state attention + normalize ----------
__global__ void __launch_bounds__(256)
ctxt_kernel()
{
    __shared__ float sm[12288];
    float* QsT = sm;
    float* Sb  = sm + 4096;
    float* Xb  = sm + 8192;

    const int j = blockIdx.x, head = blockIdx.y;
    const int l0 = j * 64;
    const float* qh  = g_q  + (head * L + l0) * HD;
    const float* kch = g_kc + (head * L + l0) * HD;
    const float* vch = g_vc + (head * L + l0) * HD;
    const float* gh  = g_gate + head * L + l0;

    const int tid = threadIdx.x;
    const int tx = tid & 15, ty = tid >> 4;

    float Greg[4];
    #pragma unroll
    for (int i = 0; i < 4; i++)
        Greg[i] = g_gcum[head * L + l0 + (ty<<2) + i];

    #pragma unroll
    for (int rep = 0; rep < 4; rep++) {
        const int g  = tid + rep * 256;
        const int r  = g >> 4;
        const int c4 = (g & 15) << 2;
        float4 q4 = *(const float4*)(qh + r * HD + c4);
        QsT[(c4+0)*64 + r] = q4.x;
        QsT[(c4+1)*64 + r] = q4.y;
        QsT[(c4+2)*64 + r] = q4.z;
        QsT[(c4+3)*64 + r] = q4.w;
        const float gs = gh[r];
        float4 v4 = *(const float4*)(vch + r * HD + c4);
        Xb[(c4+0)*64 + r] = v4.x * gs;
        Xb[(c4+1)*64 + r] = v4.y * gs;
        Xb[(c4+2)*64 + r] = v4.z * gs;
        Xb[(c4+3)*64 + r] = v4.w * gs;
    }
    {
        const float4* sp = (const float4*)(g_S + (head * 16 + j) * 4096);
        ((float4*)Sb)[tid +   0] = sp[tid +   0];
        ((float4*)Sb)[tid + 256] = sp[tid + 256];
        ((float4*)Sb)[tid + 512] = sp[tid + 512];
        ((float4*)Sb)[tid + 768] = sp[tid + 768];
    }
    __syncthreads();

    float acc[4][4] = {};
    if (j > 0) {
        #pragma unroll 4
        for (int d = 0; d < 64; d++) {
            float4 a4 = *(const float4*)(QsT + d*64 + (ty<<2));
            float4 b4 = *(const float4*)(Sb  + d*64 + (tx<<2));
            float a[4] = {a4.x, a4.y, a4.z, a4.w};
            float b[4] = {b4.x, b4.y, b4.z, b4.w};
            #pragma unroll
            for (int i = 0; i < 4; i++)
                #pragma unroll
                for (int jj = 0; jj < 4; jj++)
                    acc[i][jj] += a[i] * b[jj];
        }
    }

    float pacc[4][4] = {};
    #pragma unroll 4
    for (int d = 0; d < 64; d++) {
        float4 a4 = *(const float4*)(QsT + d*64 + (ty<<2));
        float4 b4 = *(const float4*)(Xb  + d*64 + (tx<<2));
        float a[4] = {a4.x, a4.y, a4.z, a4.w};
        float b[4] = {b4.x, b4.y, b4.z, b4.w};
        #pragma unroll
        for (int i = 0; i < 4; i++)
            #pragma unroll
            for (int jj = 0; jj < 4; jj++)
                pacc[i][jj] += a[i] * b[jj];
    }
    #pragma unroll
    for (int i = 0; i < 4; i++)
        #pragma unroll
        for (int jj = 0; jj < 4; jj++)
            if ((tx<<2) + jj > (ty<<2) + i) pacc[i][jj] = 0.0f;
    __syncthreads();

    #pragma unroll
    for (int i = 0; i < 4; i++)
        *(float4*)(Sb + ((ty<<2)+i)*64 + (tx<<2)) =
            make_float4(pacc[i][0], pacc[i][1], pacc[i][2], pacc[i][3]);
    #pragma unroll
    for (int rep = 0; rep < 4; rep++) {
        const int g  = tid + rep * 256;
        const int r  = g >> 4;
        const int c4 = (g & 15) << 2;
        *(float4*)(Xb + r*64 + c4) = *(const float4*)(kch + r * HD + c4);
    }
    __syncthreads();

    #pragma unroll 4
    for (int s = 0; s < 64; s++) {
        float a[4];
        #pragma unroll
        for (int i = 0; i < 4; i++) a[i] = Sb[((ty<<2)+i)*64 + s];
        float4 b4 = *(const float4*)(Xb + s*64 + (tx<<2));
        float b[4] = {b4.x, b4.y, b4.z, b4.w};
        #pragma unroll
        for (int i = 0; i < 4; i++)
            #pragma unroll
            for (int jj = 0; jj < 4; jj++)
                acc[i][jj] += a[i] * b[jj];
    }
    __syncthreads();

    #pragma unroll
    for (int i = 0; i < 4; i++) {
        const float gi = 1.0f / (Greg[i] + EPSF);
        #pragma unroll
        for (int jj = 0; jj < 4; jj++) acc[i][jj] *= gi;
        *(float4*)(Sb + ((ty<<2)+i)*64 + (tx<<2)) =
            make_float4(acc[i][0], acc[i][1], acc[i][2], acc[i][3]);
    }
    __syncthreads();

    if (tid < 64) {
        float ss = 0.0f;
        #pragma unroll 8
        for (int d2 = 0; d2 < 64; d2++) {
            const float c = Sb[tid*64 + d2];
            ss += c * c;
        }
        Xb[tid] = fmaxf(sqrtf(ss), EPSF);
    }
    __syncthreads();

    #pragma unroll
    for (int i = 0; i < 4; i++) {
        const float ri = 1.0f / Xb[(ty<<2) + i];
        float4 o = make_float4(acc[i][0]*ri, acc[i][1]*ri, acc[i][2]*ri, acc[i][3]*ri);
        *(float4*)(g_unit + (l0 + (ty<<2) + i) * D + head * HD + (tx<<2)) = o;
    }
}

// ---------------- kernel 6: output projection (tf32 MMA, 64x64 tiles) ----
__global__ void __launch_bounds__(256)
oproj_kernel(const float* __restrict__ wo, const float* __restrict__ bo,
             float* __restrict__ out)
{
    __shared__ float Ah[64*TFS], Bh[64*TFS];
    const int m0 = blockIdx.y * 64;
    const int n0 = blockIdx.x * 64;

    float c[1][4][4] = {};
    tf32_gemm<1>(g_unit, wo, m0, n0, c, Ah, Bh);

    const int tid = threadIdx.x, lane = tid & 31, wid = tid >> 5;
    const int mw = wid >> 1, nw = wid & 1;
    const int row = lane >> 2, qc = (lane & 3) << 1;
    const int m = m0 + mw * 16 + row;
    #pragma unroll
    for (int ns = 0; ns < 4; ns++) {
        const int nc = n0 + nw * 32 + ns * 8 + qc;
        const float b0 = bo[nc], b1 = bo[nc + 1];
        *(float2*)(out + m * D + nc) =
            make_float2(c[0][ns][0] + b0, c[0][ns][1] + b1);
        *(float2*)(out + (m + 8) * D + nc) =
            make_float2(c[0][ns][2] + b0, c[0][ns][3] + b1);
    }
}

// ---------------- launch --------------------------------------------------
extern "C" void kernel_launch(void* const* d_in, const int* in_sizes, int n_in,
                              void* d_out, int out_size)
{
    const float* x   = (const float*)d_in[0];
    const float* phi = (const float*)d_in[1];
    const float* wq  = (const float*)d_in[2];
    const float* bq  = (const float*)d_in[3];
    const float* wk  = (const float*)d_in[4];
    const float* bk  = (const float*)d_in[5];
    const float* wv  = (const float*)d_in[6];
    const float* bv  = (const float*)d_in[7];
    const float* wo  = (const float*)d_in[8];
    const float* bo  = (const float*)d_in[9];
    const float* wg  = (const float*)d_in[10];
    const float* wgb = (const float*)d_in[11];
    float* out = (float*)d_out;

    qkv_kernel    <<<dim3(8, 8, 3), 256>>>(x, wq, bq, wk, bk, wv, bv);
    conv_kernel   <<<dim3(40, 8, 2), 256>>>(phi);
    gate_kernel   <<<dim3(16, 8), 256>>>(wg, wgb);
    prescan_kernel<<<dim3(8, 5), 256>>>();
    ctxt_kernel   <<<dim3(16, 8), 256>>>();
    oproj_kernel  <<<dim3(8, 16), 256>>>(wo, bo, out);
}

// round 16
// speedup vs baseline: 1.3895x; 1.0064x over previous
#include <cuda_runtime.h>
#include <cstdint>

#define L   1024
#define D   512
#define H   8
#define HD  64
#define EPSF 1e-5f
#define SZ  (H*L*HD)          // 524288 elems per [H][L][HD] tensor

// ---------------- scratch (device globals; no allocation) ----------------
__device__ float g_q [SZ];
__device__ float g_k [SZ];
__device__ float g_v [SZ];
__device__ float g_kc[SZ];
__device__ float g_vc[SZ];
__device__ float g_gate[H*L];
__device__ float g_gcum[H*L];
__device__ float g_unit[L*D];
__device__ float g_cpart[2*4*SZ];   // conv partials: [z][chunk][H][L][HD]
__device__ float g_T[H*16*4096];    // per-tile state blocks T_j[m][n]
__device__ float g_S[H*16*4096];    // exclusive prefix of T: S_j = sum_{i<j} T_i

// Balanced triangular task map: 40 tasks per head, each <=4 s-tiles.
__device__ __forceinline__ void task_map(int t, int& lb, int& ch)
{
    int g, base;
    if      (t < 4)  { g = 0; base = 0;  }
    else if (t < 12) { g = 1; base = 4;  }
    else if (t < 24) { g = 2; base = 12; }
    else             { g = 3; base = 24; }
    const int idx = t - base;
    lb = g * 4 + idx / (g + 1);
    ch = idx % (g + 1);
}

// ================= single-pass tf32 MMA machinery ========================
__device__ __forceinline__ uint32_t f2tf32(float x)
{
    uint32_t r; asm("cvt.rna.tf32.f32 %0, %1;" : "=r"(r) : "f"(x)); return r;
}

__device__ __forceinline__ void mma_tf32(float c[4],
                                         const uint32_t a[4],
                                         const uint32_t b[2])
{
    asm("mma.sync.aligned.m16n8k8.row.col.f32.tf32.tf32.f32 "
        "{%0,%1,%2,%3}, {%4,%5,%6,%7}, {%8,%9}, {%0,%1,%2,%3};"
        : "+f"(c[0]), "+f"(c[1]), "+f"(c[2]), "+f"(c[3])
        : "r"(a[0]), "r"(a[1]), "r"(a[2]), "r"(a[3]),
          "r"(b[0]), "r"(b[1]));
}

// C[m][n] = sum_k A[m][k] * B[n][k]; block tile (64*MS)x64, K=512, 256 thr.
#define TFS 20
template<int MS>
__device__ __forceinline__ void tf32_gemm(
    const float* __restrict__ A, const float* __restrict__ B,
    int m0, int n0, float c[MS][4][4],
    float* Ah, float* Bh)
{
    const int tid  = threadIdx.x;
    const int lane = tid & 31;
    const int wid  = tid >> 5;
    const int mw   = wid >> 1;
    const int nw   = wid & 1;
    const int row  = lane >> 2;
    const int kq   = lane & 3;

    const uint32_t* uAh = (const uint32_t*)Ah;
    const uint32_t* uBh = (const uint32_t*)Bh;

    for (int k0 = 0; k0 < 512; k0 += 16) {
        __syncthreads();
        #pragma unroll
        for (int it = 0; it < MS; it++) {
            const int idx = tid + it * 256;
            const int r   = idx >> 2;
            const int c4  = (idx & 3) << 2;
            float4 g = *(const float4*)(A + (m0 + r) * 512 + k0 + c4);
            float4 hi4;
            hi4.x = __uint_as_float(f2tf32(g.x));
            hi4.y = __uint_as_float(f2tf32(g.y));
            hi4.z = __uint_as_float(f2tf32(g.z));
            hi4.w = __uint_as_float(f2tf32(g.w));
            *(float4*)(Ah + r * TFS + c4) = hi4;
        }
        {
            const int r  = tid >> 2;
            const int c4 = (tid & 3) << 2;
            float4 g = *(const float4*)(B + (n0 + r) * 512 + k0 + c4);
            float4 hi4;
            hi4.x = __uint_as_float(f2tf32(g.x));
            hi4.y = __uint_as_float(f2tf32(g.y));
            hi4.z = __uint_as_float(f2tf32(g.z));
            hi4.w = __uint_as_float(f2tf32(g.w));
            *(float4*)(Bh + r * TFS + c4) = hi4;
        }
        __syncthreads();

        #pragma unroll
        for (int k8 = 0; k8 < 16; k8 += 8) {
            uint32_t ah[MS][4], bh[4][2];
            #pragma unroll
            for (int ms = 0; ms < MS; ms++) {
                const int bi = (mw * (16 * MS) + ms * 16 + row) * TFS + k8 + kq;
                ah[ms][0] = uAh[bi];           ah[ms][1] = uAh[bi + 8*TFS];
                ah[ms][2] = uAh[bi + 4];       ah[ms][3] = uAh[bi + 8*TFS + 4];
            }
            #pragma unroll
            for (int ns = 0; ns < 4; ns++) {
                const int bi = (nw * 32 + ns * 8 + row) * TFS + k8 + kq;
                bh[ns][0] = uBh[bi];  bh[ns][1] = uBh[bi + 4];
            }
            #pragma unroll
            for (int ms = 0; ms < MS; ms++)
                #pragma unroll
                for (int ns = 0; ns < 4; ns++)
                    mma_tf32(c[ms][ns], ah[ms], bh[ns]);
        }
    }
}

// ---------------- kernel 1: fused QKV projections (tf32 MMA) -------------
__global__ void __launch_bounds__(256)
qkv_kernel(const float* __restrict__ x,
           const float* __restrict__ wq, const float* __restrict__ bq,
           const float* __restrict__ wk, const float* __restrict__ bk,
           const float* __restrict__ wv, const float* __restrict__ bv)
{
    __shared__ float Ah[128*TFS], Bh[64*TFS];
    const int z = blockIdx.z;
    const float* W    = (z == 0) ? wq : (z == 1) ? wk : wv;
    const float* bias = (z == 0) ? bq : (z == 1) ? bk : bv;
    float* out        = (z == 0) ? g_q : (z == 1) ? g_k : g_v;
    const float scale = (z == 1) ? 0.125f : 1.0f;

    const int head = blockIdx.x;
    const int m0 = blockIdx.y * 128;
    const int n0 = head * 64;

    float c[2][4][4] = {};
    tf32_gemm<2>(x, W, m0, n0, c, Ah, Bh);

    const int tid = threadIdx.x, lane = tid & 31, wid = tid >> 5;
    const int mw = wid >> 1, nw = wid & 1;
    const int row = lane >> 2, qc = (lane & 3) << 1;
    #pragma unroll
    for (int ms = 0; ms < 2; ms++) {
        const int m = m0 + mw * 32 + ms * 16 + row;
        #pragma unroll
        for (int ns = 0; ns < 4; ns++) {
            const int nc = nw * 32 + ns * 8 + qc;
            const float b0 = bias[n0 + nc], b1 = bias[n0 + nc + 1];
            float2 o0 = make_float2((c[ms][ns][0] + b0) * scale,
                                    (c[ms][ns][1] + b1) * scale);
            float2 o1 = make_float2((c[ms][ns][2] + b0) * scale,
                                    (c[ms][ns][3] + b1) * scale);
            *(float2*)(out + (head * L + m    ) * HD + nc) = o0;
            *(float2*)(out + (head * L + m + 8) * HD + nc) = o1;
        }
    }
}

// ---------------- kernel 2: causal Toeplitz conv, balanced chunks --------
// phi register-rotation: a_i(s+1) = a_{i-1}(s); 1 scalar LDS per s-step.
__global__ void __launch_bounds__(256)
conv_kernel(const float* __restrict__ phi)
{
    __shared__ float Ks[64*64];
    __shared__ float ph[130];          // +1 base shift so load index >= 0
    int lb, ch;
    task_map(blockIdx.x, lb, ch);
    const int head = blockIdx.y;
    const int z    = blockIdx.z;
    const float* src = (z ? g_v : g_k) + head * L * HD;
    float* dst = g_cpart + (z * 4 + ch) * SZ + head * L * HD;

    const int tid = threadIdx.x;
    const int tx = tid & 15, ty = tid >> 4;
    const int l0 = lb * 64;
    const int sb_beg = ch * 4;
    const int sb_end = min(sb_beg + 4, lb + 1);
    float acc[4][4] = {};

    for (int sb = sb_beg; sb < sb_end; sb++) {
        const int s0 = sb * 64;
        #pragma unroll
        for (int rep = 0; rep < 4; rep++) {
            const int g  = tid + rep * 256;
            const int r  = g >> 4;
            const int c4 = (g & 15) << 2;
            *(float4*)(Ks + r*64 + c4) = *(const float4*)(src + (s0 + r) * HD + c4);
        }
        if (tid < 127) {
            const int off = l0 - s0 - 63 + tid;
            ph[tid + 1] = (off >= 0) ? phi[off * H + head] : 0.0f;
        }
        if (tid == 127) ph[0] = 0.0f;
        __syncthreads();

        float a0 = ph[64 + (ty<<2)];
        float a1 = ph[65 + (ty<<2)];
        float a2 = ph[66 + (ty<<2)];
        float a3 = ph[67 + (ty<<2)];

        if (sb < lb) {
            #pragma unroll 4
            for (int s = 0; s < 64; s++) {
                float4 b4 = *(const float4*)(Ks + s*64 + (tx<<2));
                float b[4] = {b4.x, b4.y, b4.z, b4.w};
                float a[4] = {a0, a1, a2, a3};
                #pragma unroll
                for (int i = 0; i < 4; i++)
                    #pragma unroll
                    for (int j = 0; j < 4; j++) acc[i][j] += a[i] * b[j];
                a3 = a2; a2 = a1; a1 = a0;
                a0 = ph[63 + (ty<<2) - s];
            }
        } else {  // diagonal tile: causal mask l >= s
            #pragma unroll 4
            for (int s = 0; s < 64; s++) {
                float4 b4 = *(const float4*)(Ks + s*64 + (tx<<2));
                float b[4] = {b4.x, b4.y, b4.z, b4.w};
                float a[4] = {a0, a1, a2, a3};
                #pragma unroll
                for (int i = 0; i < 4; i++) {
                    const int ll = (ty<<2) + i;
                    const float av = (ll >= s) ? a[i] : 0.0f;
                    #pragma unroll
                    for (int j = 0; j < 4; j++) acc[i][j] += av * b[j];
                }
                a3 = a2; a2 = a1; a1 = a0;
                a0 = ph[63 + (ty<<2) - s];
            }
        }
        __syncthreads();
    }

    #pragma unroll
    for (int i = 0; i < 4; i++) {
        float4 o = make_float4(acc[i][0], acc[i][1], acc[i][2], acc[i][3]);
        *(float4*)(dst + (l0 + (ty<<2) + i) * HD + (tx<<2)) = o;
    }
}

// ---------------- kernel 3: conv-finalize + gates + state block T_j ------
__global__ void __launch_bounds__(256)
gate_kernel(const float* __restrict__ wg, const float* __restrict__ wgb)
{
    __shared__ float sm[12288];
    float* KsT   = sm;                  // [n][l] finalized Kc transposed
    float* wgT   = sm + 4096;           // [n][m]; phase B: Ksn [s][n]
    float* Vcs   = sm + 8192;           // [s][m] finalized Vc
    float* red   = sm;                  // alias after phase A reads
    float* gvals = sm + 1536;

    const int lb = blockIdx.x, head = blockIdx.y;
    const int l0 = lb * 64;
    const int nchunks = (lb >> 2) + 1;
    const float* kp = g_cpart + head * L * HD + l0 * HD;            // z=0,ch=0
    const float* vp = g_cpart + 4 * SZ + head * L * HD + l0 * HD;   // z=1,ch=0

    const int tid = threadIdx.x;
    const int tx = tid & 15, ty = tid >> 4;

    #pragma unroll
    for (int rep = 0; rep < 4; rep++) {
        const int g  = tid + rep * 256;
        const int r  = g >> 4;
        const int c4 = (g & 15) << 2;
        const int off = r * HD + c4;

        float4 kv = *(const float4*)(kp + off);
        for (int c = 1; c < nchunks; c++) {
            float4 p = *(const float4*)(kp + c * SZ + off);
            kv.x += p.x; kv.y += p.y; kv.z += p.z; kv.w += p.w;
        }
        *(float4*)(g_kc + (head * L + l0 + r) * HD + c4) = kv;
        KsT[(c4+0)*64 + r] = kv.x;
        KsT[(c4+1)*64 + r] = kv.y;
        KsT[(c4+2)*64 + r] = kv.z;
        KsT[(c4+3)*64 + r] = kv.w;

        float4 vv = *(const float4*)(vp + off);
        for (int c = 1; c < nchunks; c++) {
            float4 p = *(const float4*)(vp + c * SZ + off);
            vv.x += p.x; vv.y += p.y; vv.z += p.z; vv.w += p.w;
        }
        *(float4*)(g_vc + (head * L + l0 + r) * HD + c4) = vv;
        *(float4*)(Vcs + r*64 + c4) = vv;

        float4 wv = *(const float4*)(wg + r * 64 + c4);
        wgT[(c4+0)*64 + r] = wv.x;
        wgT[(c4+1)*64 + r] = wv.y;
        wgT[(c4+2)*64 + r] = wv.z;
        wgT[(c4+3)*64 + r] = wv.w;
    }
    __syncthreads();

    // Phase A: Tg[l][m] = sum_n kc[l,n]*W[m,n]; psum = <Tg[l], vc[l]>
    float acc[4][4] = {};
    #pragma unroll 4
    for (int n = 0; n < 64; n++) {
        float4 a4 = *(const float4*)(KsT + n*64 + (ty<<2));
        float4 b4 = *(const float4*)(wgT + n*64 + (tx<<2));
        float a[4] = {a4.x, a4.y, a4.z, a4.w};
        float b[4] = {b4.x, b4.y, b4.z, b4.w};
        #pragma unroll
        for (int i = 0; i < 4; i++)
            #pragma unroll
            for (int j = 0; j < 4; j++)
                acc[i][j] += a[i] * b[j];
    }
    float psum[4];
    #pragma unroll
    for (int i = 0; i < 4; i++) {
        float4 v4 = *(const float4*)(Vcs + ((ty<<2)+i)*64 + (tx<<2));
        psum[i] = acc[i][0]*v4.x + acc[i][1]*v4.y + acc[i][2]*v4.z + acc[i][3]*v4.w;
    }
    __syncthreads();
    #pragma unroll
    for (int i = 0; i < 4; i++)
        red[((ty<<2)+i)*16 + tx] = psum[i];
    __syncthreads();

    if (tid < 64) {
        float s = 0.0f;
        #pragma unroll
        for (int t = 0; t < 16; t++) s += red[tid*16 + t];
        const float r = fmaxf(s + wgb[0], 0.0f);
        const float gv = r * r + EPSF;
        g_gate[head * L + l0 + tid] = gv;
        gvals[tid] = gv;
    }
    __syncthreads();

    // Phase B: reload own finalized Kc (L1-hot) natural into wgT area
    float* Ksn = wgT;
    const float* kch = g_kc + (head * L + l0) * HD;
    #pragma unroll
    for (int rep = 0; rep < 4; rep++) {
        const int g  = tid + rep * 256;
        const int r  = g >> 4;
        const int c4 = (g & 15) << 2;
        *(float4*)(Ksn + r*64 + c4) = *(const float4*)(kch + r * HD + c4);
    }
    #pragma unroll
    for (int k = 0; k < 4; k++) {
        const int f = tid + k * 256;
        const float gv = gvals[f >> 4];
        float4 v = ((float4*)Vcs)[f];
        v.x *= gv; v.y *= gv; v.z *= gv; v.w *= gv;
        ((float4*)Vcs)[f] = v;
    }
    __syncthreads();

    float tacc[4][4] = {};
    #pragma unroll 4
    for (int s = 0; s < 64; s++) {
        float4 a4 = *(const float4*)(Vcs + s*64 + (ty<<2));
        float4 b4 = *(const float4*)(Ksn + s*64 + (tx<<2));
        float a[4] = {a4.x, a4.y, a4.z, a4.w};
        float b[4] = {b4.x, b4.y, b4.z, b4.w};
        #pragma unroll
        for (int i = 0; i < 4; i++)
            #pragma unroll
            for (int j = 0; j < 4; j++)
                tacc[i][j] += a[i] * b[j];
    }
    float* dst = g_T + (head * 16 + lb) * 4096;
    #pragma unroll
    for (int i = 0; i < 4; i++)
        *(float4*)(dst + ((ty<<2)+i)*64 + (tx<<2)) =
            make_float4(tacc[i][0], tacc[i][1], tacc[i][2], tacc[i][3]);
}

// ---------------- kernel 4: prescan (T prefix + gate scan) ---------------
// grid (8, 5): y<4 -> exclusive running sum of T tiles with FULL 16-deep
// prefetch (all loads independent & in flight before the serial accumulate;
// ascending-i order -> g_S bitwise identical); y==4 -> gate scan.
__global__ void __launch_bounds__(256)
prescan_kernel()
{
    const int head = blockIdx.x;
    const int part = blockIdx.y;
    if (part < 4) {
        const int f = part * 256 + threadIdx.x;      // float4 idx in [0,1024)
        const float4* tbase = (const float4*)(g_T + head * 16 * 4096);
        float4* sbase = (float4*)(g_S + head * 16 * 4096);
        float4 p[16];
        #pragma unroll
        for (int i = 0; i < 16; i++)
            p[i] = tbase[i * 1024 + f];              // 16 independent LDG.128
        float4 run = make_float4(0.f, 0.f, 0.f, 0.f);
        #pragma unroll
        for (int i = 0; i < 16; i++) {
            sbase[i * 1024 + f] = run;
            run.x += p[i].x; run.y += p[i].y; run.z += p[i].z; run.w += p[i].w;
        }
    } else {
        __shared__ float sb[256];
        const int tid = threadIdx.x;
        const float* gfull = g_gate + head * L;
        float4 gv = *(const float4*)(gfull + tid * 4);
        const float p0 = gv.x;
        const float p1 = p0 + gv.y;
        const float p2 = p1 + gv.z;
        const float p3 = p2 + gv.w;
        sb[tid] = p3;
        __syncthreads();
        for (int off = 1; off < 256; off <<= 1) {
            const float v = (tid >= off) ? sb[tid - off] : 0.0f;
            __syncthreads();
            sb[tid] += v;
            __syncthreads();
        }
        const float excl = sb[tid] - p3;
        float4 o = make_float4(excl + p0, excl + p1, excl + p2, excl + p3);
        *(float4*)(g_gcum + head * L + tid * 4) = o;
    }
}

// ---------------- kernel 5: chunked-state attention + normalize ----------
__global__ void __launch_bounds__(256)
ctxt_kernel()
{
    __shared__ float sm[12288];
    float* QsT = sm;
    float* Sb  = sm + 4096;
    float* Xb  = sm + 8192;

    const int j = blockIdx.x, head = blockIdx.y;
    const int l0 = j * 64;
    const float* qh  = g_q  + (head * L + l0) * HD;
    const float* kch = g_kc + (head * L + l0) * HD;
    const float* vch = g_vc + (head * L + l0) * HD;
    const float* gh  = g_gate + head * L + l0;

    const int tid = threadIdx.x;
    const int tx = tid & 15, ty = tid >> 4;

    float Greg[4];
    #pragma unroll
    for (int i = 0; i < 4; i++)
        Greg[i] = g_gcum[head * L + l0 + (ty<<2) + i];

    #pragma unroll
    for (int rep = 0; rep < 4; rep++) {
        const int g  = tid + rep * 256;
        const int r  = g >> 4;
        const int c4 = (g & 15) << 2;
        float4 q4 = *(const float4*)(qh + r * HD + c4);
        QsT[(c4+0)*64 + r] = q4.x;
        QsT[(c4+1)*64 + r] = q4.y;
        QsT[(c4+2)*64 + r] = q4.z;
        QsT[(c4+3)*64 + r] = q4.w;
        const float gs = gh[r];
        float4 v4 = *(const float4*)(vch + r * HD + c4);
        Xb[(c4+0)*64 + r] = v4.x * gs;
        Xb[(c4+1)*64 + r] = v4.y * gs;
        Xb[(c4+2)*64 + r] = v4.z * gs;
        Xb[(c4+3)*64 + r] = v4.w * gs;
    }
    {
        const float4* sp = (const float4*)(g_S + (head * 16 + j) * 4096);
        ((float4*)Sb)[tid +   0] = sp[tid +   0];
        ((float4*)Sb)[tid + 256] = sp[tid + 256];
        ((float4*)Sb)[tid + 512] = sp[tid + 512];
        ((float4*)Sb)[tid + 768] = sp[tid + 768];
    }
    __syncthreads();

    float acc[4][4] = {};
    if (j > 0) {
        #pragma unroll 4
        for (int d = 0; d < 64; d++) {
            float4 a4 = *(const float4*)(QsT + d*64 + (ty<<2));
            float4 b4 = *(const float4*)(Sb  + d*64 + (tx<<2));
            float a[4] = {a4.x, a4.y, a4.z, a4.w};
            float b[4] = {b4.x, b4.y, b4.z, b4.w};
            #pragma unroll
            for (int i = 0; i < 4; i++)
                #pragma unroll
                for (int jj = 0; jj < 4; jj++)
                    acc[i][jj] += a[i] * b[jj];
        }
    }

    float pacc[4][4] = {};
    #pragma unroll 4
    for (int d = 0; d < 64; d++) {
        float4 a4 = *(const float4*)(QsT + d*64 + (ty<<2));
        float4 b4 = *(const float4*)(Xb  + d*64 + (tx<<2));
        float a[4] = {a4.x, a4.y, a4.z, a4.w};
        float b[4] = {b4.x, b4.y, b4.z, b4.w};
        #pragma unroll
        for (int i = 0; i < 4; i++)
            #pragma unroll
            for (int jj = 0; jj < 4; jj++)
                pacc[i][jj] += a[i] * b[jj];
    }
    #pragma unroll
    for (int i = 0; i < 4; i++)
        #pragma unroll
        for (int jj = 0; jj < 4; jj++)
            if ((tx<<2) + jj > (ty<<2) + i) pacc[i][jj] = 0.0f;
    __syncthreads();

    #pragma unroll
    for (int i = 0; i < 4; i++)
        *(float4*)(Sb + ((ty<<2)+i)*64 + (tx<<2)) =
            make_float4(pacc[i][0], pacc[i][1], pacc[i][2], pacc[i][3]);
    #pragma unroll
    for (int rep = 0; rep < 4; rep++) {
        const int g  = tid + rep * 256;
        const int r  = g >> 4;
        const int c4 = (g & 15) << 2;
        *(float4*)(Xb + r*64 + c4) = *(const float4*)(kch + r * HD + c4);
    }
    __syncthreads();

    #pragma unroll 4
    for (int s = 0; s < 64; s++) {
        float a[4];
        #pragma unroll
        for (int i = 0; i < 4; i++) a[i] = Sb[((ty<<2)+i)*64 + s];
        float4 b4 = *(const float4*)(Xb + s*64 + (tx<<2));
        float b[4] = {b4.x, b4.y, b4.z, b4.w};
        #pragma unroll
        for (int i = 0; i < 4; i++)
            #pragma unroll
            for (int jj = 0; jj < 4; jj++)
                acc[i][jj] += a[i] * b[jj];
    }
    __syncthreads();

    #pragma unroll
    for (int i = 0; i < 4; i++) {
        const float gi = 1.0f / (Greg[i] + EPSF);
        #pragma unroll
        for (int jj = 0; jj < 4; jj++) acc[i][jj] *= gi;
        *(float4*)(Sb + ((ty<<2)+i)*64 + (tx<<2)) =
            make_float4(acc[i][0], acc[i][1], acc[i][2], acc[i][3]);
    }
    __syncthreads();

    if (tid < 64) {
        float ss = 0.0f;
        #pragma unroll 8
        for (int d2 = 0; d2 < 64; d2++) {
            const float c = Sb[tid*64 + d2];
            ss += c * c;
        }
        Xb[tid] = fmaxf(sqrtf(ss), EPSF);
    }
    __syncthreads();

    #pragma unroll
    for (int i = 0; i < 4; i++) {
        const float ri = 1.0f / Xb[(ty<<2) + i];
        float4 o = make_float4(acc[i][0]*ri, acc[i][1]*ri, acc[i][2]*ri, acc[i][3]*ri);
        *(float4*)(g_unit + (l0 + (ty<<2) + i) * D + head * HD + (tx<<2)) = o;
    }
}

// ---------------- kernel 6: output projection (tf32 MMA, 64x64 tiles) ----
__global__ void __launch_bounds__(256)
oproj_kernel(const float* __restrict__ wo, const float* __restrict__ bo,
             float* __restrict__ out)
{
    __shared__ float Ah[64*TFS], Bh[64*TFS];
    const int m0 = blockIdx.y * 64;
    const int n0 = blockIdx.x * 64;

    float c[1][4][4] = {};
    tf32_gemm<1>(g_unit, wo, m0, n0, c, Ah, Bh);

    const int tid = threadIdx.x, lane = tid & 31, wid = tid >> 5;
    const int mw = wid >> 1, nw = wid & 1;
    const int row = lane >> 2, qc = (lane & 3) << 1;
    const int m = m0 + mw * 16 + row;
    #pragma unroll
    for (int ns = 0; ns < 4; ns++) {
        const int nc = n0 + nw * 32 + ns * 8 + qc;
        const float b0 = bo[nc], b1 = bo[nc + 1];
        *(float2*)(out + m * D + nc) =
            make_float2(c[0][ns][0] + b0, c[0][ns][1] + b1);
        *(float2*)(out + (m + 8) * D + nc) =
            make_float2(c[0][ns][2] + b0, c[0][ns][3] + b1);
    }
}

// ---------------- launch --------------------------------------------------
extern "C" void kernel_launch(void* const* d_in, const int* in_sizes, int n_in,
                              void* d_out, int out_size)
{
    const float* x   = (const float*)d_in[0];
    const float* phi = (const float*)d_in[1];
    const float* wq  = (const float*)d_in[2];
    const float* bq  = (const float*)d_in[3];
    const float* wk  = (const float*)d_in[4];
    const float* bk  = (const float*)d_in[5];
    const float* wv  = (const float*)d_in[6];
    const float* bv  = (const float*)d_in[7];
    const float* wo  = (const float*)d_in[8];
    const float* bo  = (const float*)d_in[9];
    const float* wg  = (const float*)d_in[10];
    const float* wgb = (const float*)d_in[11];
    float* out = (float*)d_out;

    qkv_kernel    <<<dim3(8, 8, 3), 256>>>(x, wq, bq, wk, bk, wv, bv);
    conv_kernel   <<<dim3(40, 8, 2), 256>>>(phi);
    gate_kernel   <<<dim3(16, 8), 256>>>(wg, wgb);
    prescan_kernel<<<dim3(8, 5), 256>>>();
    ctxt_kernel   <<<dim3(16, 8), 256>>>();
    oproj_kernel  <<<dim3(8, 16), 256>>>(wo, bo, out);
}